// round 14
// baseline (speedup 1.0000x reference)
#include <cuda_runtime.h>
#include <cuda_bf16.h>
#include <math.h>
#include <stdint.h>

#define TT 1536
#define CC 1536
#define HH 8
#define HK 64
#define HV 192
#define FF 192
#define QKC 512
#define LLP 3072
typedef __nv_bfloat16 bf16;

// ---------------- scratch ----------------
__device__ bf16 g_xn_h[TT*CC],  g_xn_l[TT*CC];
__device__ bf16 g_wq_h[QKC*CC], g_wq_l[QKC*CC];
__device__ bf16 g_wk_h[QKC*CC], g_wk_l[QKC*CC];
__device__ bf16 g_wv_h[CC*CC],  g_wv_l[CC*CC];
__device__ bf16 g_wr_h[QKC*FF], g_wr_l[QKC*FF];
__device__ bf16 g_wo_h[CC*CC],  g_wo_l[CC*CC];
__device__ bf16 g_w1_h[2*CC*CC],g_w1_l[2*CC*CC];
__device__ bf16 g_w2_h[CC*2*CC],g_w2_l[CC*2*CC];
__device__ bf16 g_qw_h[TT*QKC], g_qw_l[TT*QKC];
__device__ bf16 g_qr_h[TT*QKC], g_qr_l[TT*QKC];
__device__ bf16 g_k_h[TT*QKC],  g_k_l[TT*QKC];
__device__ float g_vf[TT*CC];
__device__ bf16 g_vT_h[CC*TT],  g_vT_l[CC*TT];
__device__ bf16 g_pos_h[LLP*FF],g_pos_l[LLP*FF];
__device__ bf16 g_rk_h[LLP*QKC],g_rk_l[LLP*QKC];
__device__ float g_cont[HH*TT*TT];
__device__ float g_rel[(size_t)HH*TT*LLP];
__device__ bf16 g_at_h[HH*TT*TT], g_at_l[HH*TT*TT];
__device__ bf16 g_o_h[TT*CC],   g_o_l[TT*CC];
__device__ float g_y[TT*CC];
__device__ bf16 g_yn_h[TT*CC],  g_yn_l[TT*CC];
__device__ bf16 g_h1_h[TT*2*CC],g_h1_l[TT*2*CC];
__device__ float g_part[2*TT*CC];     // split-K partials

// ---------------- helpers ----------------
__device__ __forceinline__ uint32_t smem_u32(const void* p) {
    uint32_t a;
    asm("{ .reg .u64 t; cvta.to.shared.u64 t, %1; cvt.u32.u64 %0, t; }" : "=r"(a) : "l"(p));
    return a;
}
__device__ __forceinline__ void mma_bf16(float* c, const uint32_t* a, const uint32_t* b) {
    asm volatile("mma.sync.aligned.m16n8k16.row.col.f32.bf16.bf16.f32 "
        "{%0,%1,%2,%3},{%4,%5,%6,%7},{%8,%9},{%0,%1,%2,%3};"
        : "+f"(c[0]), "+f"(c[1]), "+f"(c[2]), "+f"(c[3])
        : "r"(a[0]), "r"(a[1]), "r"(a[2]), "r"(a[3]), "r"(b[0]), "r"(b[1]));
}
__device__ __forceinline__ void ldsm4(uint32_t* r, uint32_t addr) {
    asm volatile("ldmatrix.sync.aligned.m8n8.x4.shared.b16 {%0,%1,%2,%3}, [%4];"
        : "=r"(r[0]), "=r"(r[1]), "=r"(r[2]), "=r"(r[3]) : "r"(addr));
}
__device__ __forceinline__ void cpasync16(uint32_t dst, const void* src, uint32_t sz) {
    asm volatile("cp.async.ca.shared.global [%0], [%1], 16, %2;"
                 :: "r"(dst), "l"(src), "r"(sz) : "memory");
}
__device__ __forceinline__ void cp_commit() { asm volatile("cp.async.commit_group;" ::: "memory"); }
__device__ __forceinline__ void cp_wait0()  { asm volatile("cp.async.wait_group 0;" ::: "memory"); }
__device__ __forceinline__ uint32_t pack_bf2(float a, float b) {
    __nv_bfloat162 t = __floats2bfloat162_rn(a, b);
    return *reinterpret_cast<uint32_t*>(&t);
}
__device__ __forceinline__ float bfr(float x) { return __bfloat162float(__float2bfloat16(x)); }
__device__ __forceinline__ void split_bf(float v, bf16& h, bf16& l) {
    h = __float2bfloat16(v);
    l = __float2bfloat16(v - __bfloat162float(h));
}

// ================= tile 128x128 GEMM, 128 threads, warp tile 64x64 =================
#define R128 80
#define T128_AH 0
#define T128_AL 10240
#define T128_BH 20480
#define T128_BL 30720
#define T128_STG 40960
#define T128_SM (2*T128_STG)

__global__ __launch_bounds__(128, 2)
void tgemm128_kernel(int M, int N, int K,
                  const bf16* __restrict__ Ah, const bf16* __restrict__ Al, int lda, long long sA,
                  const bf16* __restrict__ Bh, const bf16* __restrict__ Bl, int ldb, long long sB,
                  float* __restrict__ Cf, bf16* __restrict__ Ch, bf16* __restrict__ Cl,
                  int ldc, long long sC,
                  const float* __restrict__ bias,
                  const float* __restrict__ Rp, int ldr, long long sR,
                  float alpha, int relu, int win)
{
    extern __shared__ char smem[];
    uint32_t sbase = smem_u32(smem);
    int tid = threadIdx.x, wid = tid >> 5, lane = tid & 31;
    int grp = lane >> 2, tig = lane & 3;
    int wm = wid & 1, wn = wid >> 1;          // 2m x 2n warps; warp tile 64x64
    int z = blockIdx.z;
    Ah += (long long)z * sA;  Al += (long long)z * sA;
    Bh += (long long)z * sB;  Bl += (long long)z * sB;
    const float* Rb = Rp ? Rp + (long long)z * sR : nullptr;
    int bm = blockIdx.y * 128;
    int bn = win ? (11 - blockIdx.y + blockIdx.x) * 128 : blockIdx.x * 128;

    const int nch = K >> 5;
    // staging: 1 thread per row (128 rows), 64B per matrix per chunk
    const uint32_t sdst = (uint32_t)tid * R128;
    const bf16* gAh = Ah + (size_t)(bm + tid) * lda;
    const bf16* gAl = Al + (size_t)(bm + tid) * lda;
    const bf16* gBh = Bh + (size_t)(bn + tid) * ldb;
    const bf16* gBl = Bl + (size_t)(bn + tid) * ldb;

    const uint32_t lA = (uint32_t)(lane & 15) * R128 + (uint32_t)(lane >> 4) * 16;
    const uint32_t lB = ((uint32_t)((lane >> 4) * 8 + (lane & 7))) * R128 + (uint32_t)((lane >> 3) & 1) * 16;

    float acc[4][8][4];
#pragma unroll
    for (int a = 0; a < 4; a++)
#pragma unroll
        for (int b = 0; b < 8; b++)
#pragma unroll
            for (int r = 0; r < 4; r++) acc[a][b][r] = 0.f;

    {   // prologue: stage 0 <- chunk 0
        uint32_t st = sbase + sdst;
#pragma unroll
        for (int i = 0; i < 4; i++) {
            cpasync16(st + T128_AH + i * 16, gAh + i * 8, 16);
            cpasync16(st + T128_AL + i * 16, gAl + i * 8, 16);
            cpasync16(st + T128_BH + i * 16, gBh + i * 8, 16);
            cpasync16(st + T128_BL + i * 16, gBl + i * 8, 16);
        }
        cp_commit();
    }

    for (int c = 0; c < nch; c++) {
        cp_wait0();
        __syncthreads();

        if (c + 1 < nch) {
            uint32_t st = sbase + ((c + 1) & 1) * T128_STG + sdst;
            int k0 = (c + 1) << 5;
#pragma unroll
            for (int i = 0; i < 4; i++) {
                cpasync16(st + T128_AH + i * 16, gAh + k0 + i * 8, 16);
                cpasync16(st + T128_AL + i * 16, gAl + k0 + i * 8, 16);
                cpasync16(st + T128_BH + i * 16, gBh + k0 + i * 8, 16);
                cpasync16(st + T128_BL + i * 16, gBl + k0 + i * 8, 16);
            }
        }
        cp_commit();

        uint32_t stg = sbase + (c & 1) * T128_STG;
#pragma unroll
        for (int ks = 0; ks < 2; ks++) {
            uint32_t koff = (uint32_t)ks * 32;
            uint32_t bh[4][4], bl[4][4];
#pragma unroll
            for (int p = 0; p < 4; p++) {
                uint32_t ba = stg + (uint32_t)(wn * 64 + p * 16) * R128 + koff + lB;
                ldsm4(bh[p], ba + T128_BH);
                ldsm4(bl[p], ba + T128_BL);
            }
#pragma unroll
            for (int ms = 0; ms < 4; ms++) {
                uint32_t aa = stg + (uint32_t)(wm * 64 + ms * 16) * R128 + koff + lA;
                uint32_t ah[4], al[4];
                ldsm4(ah, aa + T128_AH);
                ldsm4(al, aa + T128_AL);
#pragma unroll
                for (int ns = 0; ns < 8; ns++) {
                    uint32_t* bhp = &bh[ns >> 1][(ns & 1) * 2];
                    uint32_t* blp = &bl[ns >> 1][(ns & 1) * 2];
                    mma_bf16(acc[ms][ns], ah, bhp);
                    mma_bf16(acc[ms][ns], ah, blp);
                    mma_bf16(acc[ms][ns], al, bhp);
                }
            }
        }
    }

    // epilogue
    Cf  = Cf  ? Cf  + (long long)z * sC : nullptr;
    Ch  = Ch  ? Ch  + (long long)z * sC : nullptr;
    Cl  = Cl  ? Cl  + (long long)z * sC : nullptr;
    const bool has_bias = (bias != nullptr);
#pragma unroll
    for (int ms = 0; ms < 4; ms++) {
        int row0 = bm + wm * 64 + ms * 16 + grp;
#pragma unroll
        for (int ns = 0; ns < 8; ns++) {
            int col = bn + wn * 64 + ns * 8 + (tig << 1);
            float b0 = has_bias ? bias[col]     : 0.f;
            float b1v = has_bias ? bias[col + 1] : 0.f;
#pragma unroll
            for (int h = 0; h < 2; h++) {
                int m = row0 + h * 8;
                float v0 = fmaf(alpha, acc[ms][ns][h * 2 + 0], b0);
                float v1 = fmaf(alpha, acc[ms][ns][h * 2 + 1], b1v);
                if (relu) { v0 = fmaxf(v0, 0.f); v1 = fmaxf(v1, 0.f); }
                if (Cf) {
                    if (Rb) {
                        const float* rp = Rb + (size_t)m * ldr + col;
                        v0 += rp[0]; v1 += rp[1];
                    }
                    *(float2*)(Cf + (size_t)m * ldc + col) = make_float2(v0, v1);
                } else {
                    *(uint32_t*)(Ch + (size_t)m * ldc + col) = pack_bf2(v0, v1);
                    *(uint32_t*)(Cl + (size_t)m * ldc + col) =
                        pack_bf2(v0 - bfr(v0), v1 - bfr(v1));
                }
            }
        }
    }
}

// ================= tile 128x64 GEMM (small-N) =================
#define R64 80
#define T64_AH 0
#define T64_AL 10240
#define T64_BH 20480
#define T64_BL 25600
#define T64_STG 30720
#define T64_SM (2*T64_STG)

__global__ __launch_bounds__(256, 2)
void tgemm64_kernel(int M, int N, int K,
                  const bf16* __restrict__ Ah, const bf16* __restrict__ Al, int lda, long long sA,
                  const bf16* __restrict__ Bh, const bf16* __restrict__ Bl, int ldb, long long sB,
                  float* __restrict__ Cf, bf16* __restrict__ Ch, bf16* __restrict__ Cl,
                  int ldc, long long sC, float alpha)
{
    extern __shared__ char smem[];
    uint32_t sbase = smem_u32(smem);
    int tid = threadIdx.x, wid = tid >> 5, lane = tid & 31;
    int grp = lane >> 2, tig = lane & 3;
    int wm = wid & 3, wn = wid >> 2;
    int z = blockIdx.z;
    Ah += (long long)z * sA;  Al += (long long)z * sA;
    Bh += (long long)z * sB;  Bl += (long long)z * sB;
    int bm = blockIdx.y * 128;
    int bn = blockIdx.x * 64;

    const int nch = K >> 5;
    const int sra = tid >> 1, ssa = tid & 1;
    const int srb = tid >> 2, ssb = tid & 3;
    const uint32_t dstA = sra * R64 + ssa * 32;
    const uint32_t dstB = srb * R64 + ssb * 16;

    const bf16* gAh = Ah + (size_t)(bm + sra) * lda + ssa * 16;
    const bf16* gAl = Al + (size_t)(bm + sra) * lda + ssa * 16;
    const bf16* gBh = Bh + (size_t)(bn + srb) * ldb + ssb * 8;
    const bf16* gBl = Bl + (size_t)(bn + srb) * ldb + ssb * 8;

    const uint32_t lA = (uint32_t)(lane & 15) * R64 + (uint32_t)(lane >> 4) * 16;
    const uint32_t lB = ((uint32_t)((lane >> 4) * 8 + (lane & 7))) * R64 + (uint32_t)((lane >> 3) & 1) * 16;

    float acc[2][4][4];
#pragma unroll
    for (int a = 0; a < 2; a++)
#pragma unroll
        for (int b = 0; b < 4; b++)
#pragma unroll
            for (int r = 0; r < 4; r++) acc[a][b][r] = 0.f;

    {
        uint32_t st = sbase;
        cpasync16(st + T64_AH + dstA,      gAh,     16);
        cpasync16(st + T64_AH + dstA + 16, gAh + 8, 16);
        cpasync16(st + T64_AL + dstA,      gAl,     16);
        cpasync16(st + T64_AL + dstA + 16, gAl + 8, 16);
        cpasync16(st + T64_BH + dstB,      gBh,     16);
        cpasync16(st + T64_BL + dstB,      gBl,     16);
        cp_commit();
    }

    for (int c = 0; c < nch; c++) {
        cp_wait0();
        __syncthreads();

        if (c + 1 < nch) {
            uint32_t st = sbase + ((c + 1) & 1) * T64_STG;
            int k0 = (c + 1) << 5;
            cpasync16(st + T64_AH + dstA,      gAh + k0,     16);
            cpasync16(st + T64_AH + dstA + 16, gAh + k0 + 8, 16);
            cpasync16(st + T64_AL + dstA,      gAl + k0,     16);
            cpasync16(st + T64_AL + dstA + 16, gAl + k0 + 8, 16);
            cpasync16(st + T64_BH + dstB,      gBh + k0,     16);
            cpasync16(st + T64_BL + dstB,      gBl + k0,     16);
        }
        cp_commit();

        uint32_t stg = sbase + (c & 1) * T64_STG;
#pragma unroll
        for (int ks = 0; ks < 2; ks++) {
            uint32_t koff = (uint32_t)ks * 32;
            uint32_t bh[2][4], bl[2][4];
#pragma unroll
            for (int p = 0; p < 2; p++) {
                uint32_t ba = stg + (uint32_t)(wn * 32 + p * 16) * R64 + koff + lB;
                ldsm4(bh[p], ba + T64_BH);
                ldsm4(bl[p], ba + T64_BL);
            }
#pragma unroll
            for (int ms = 0; ms < 2; ms++) {
                uint32_t aa = stg + (uint32_t)(wm * 32 + ms * 16) * R64 + koff + lA;
                uint32_t ah[4], al[4];
                ldsm4(ah, aa + T64_AH);
                ldsm4(al, aa + T64_AL);
#pragma unroll
                for (int ns = 0; ns < 4; ns++) {
                    uint32_t* bhp = &bh[ns >> 1][(ns & 1) * 2];
                    uint32_t* blp = &bl[ns >> 1][(ns & 1) * 2];
                    mma_bf16(acc[ms][ns], ah, bhp);
                    mma_bf16(acc[ms][ns], ah, blp);
                    mma_bf16(acc[ms][ns], al, bhp);
                }
            }
        }
    }

    Cf  = Cf  ? Cf  + (long long)z * sC : nullptr;
    Ch  = Ch  ? Ch  + (long long)z * sC : nullptr;
    Cl  = Cl  ? Cl  + (long long)z * sC : nullptr;
#pragma unroll
    for (int ms = 0; ms < 2; ms++) {
        int row0 = bm + wm * 32 + ms * 16 + grp;
#pragma unroll
        for (int ns = 0; ns < 4; ns++) {
            int col = bn + wn * 32 + ns * 8 + (tig << 1);
#pragma unroll
            for (int h = 0; h < 2; h++) {
                int m = row0 + h * 8;
                float v0 = alpha * acc[ms][ns][h * 2 + 0];
                float v1 = alpha * acc[ms][ns][h * 2 + 1];
                if (Cf) {
                    *(float2*)(Cf + (size_t)m * ldc + col) = make_float2(v0, v1);
                } else {
                    *(uint32_t*)(Ch + (size_t)m * ldc + col) = pack_bf2(v0, v1);
                    *(uint32_t*)(Cl + (size_t)m * ldc + col) =
                        pack_bf2(v0 - bfr(v0), v1 - bfr(v1));
                }
            }
        }
    }
}

// ---------------- split-K combine ----------------
__global__ void combine_kernel(const float* __restrict__ p, int n, int ld,
                               const float* __restrict__ bias, const float* __restrict__ res,
                               float* __restrict__ outf,
                               bf16* __restrict__ oh, bf16* __restrict__ ol,
                               const float* __restrict__ bias2,
                               bf16* __restrict__ oh2, bf16* __restrict__ ol2)
{
    int i4 = blockIdx.x * 256 + threadIdx.x;
    if (i4 * 4 >= n) return;
    int i = i4 * 4;
    float4 a = *(const float4*)(p + i);
    float4 b = *(const float4*)(p + n + i);
    float4 s = make_float4(a.x + b.x, a.y + b.y, a.z + b.z, a.w + b.w);
    int col = i % ld;
    float4 v = s;
    if (bias) {
        float4 bb = *(const float4*)(bias + col);
        v.x += bb.x; v.y += bb.y; v.z += bb.z; v.w += bb.w;
    }
    if (res) {
        float4 r = *(const float4*)(res + i);
        v.x += r.x; v.y += r.y; v.z += r.z; v.w += r.w;
    }
    if (outf) {
        *(float4*)(outf + i) = v;
    } else {
        *(uint32_t*)(oh + i)     = pack_bf2(v.x, v.y);
        *(uint32_t*)(oh + i + 2) = pack_bf2(v.z, v.w);
        *(uint32_t*)(ol + i)     = pack_bf2(v.x - bfr(v.x), v.y - bfr(v.y));
        *(uint32_t*)(ol + i + 2) = pack_bf2(v.z - bfr(v.z), v.w - bfr(v.w));
        if (oh2) {
            float4 b2v = *(const float4*)(bias2 + col);
            float4 u = make_float4(s.x + b2v.x, s.y + b2v.y, s.z + b2v.z, s.w + b2v.w);
            *(uint32_t*)(oh2 + i)     = pack_bf2(u.x, u.y);
            *(uint32_t*)(oh2 + i + 2) = pack_bf2(u.z, u.w);
            *(uint32_t*)(ol2 + i)     = pack_bf2(u.x - bfr(u.x), u.y - bfr(u.y));
            *(uint32_t*)(ol2 + i + 2) = pack_bf2(u.z - bfr(u.z), u.w - bfr(u.w));
        }
    }
}

// ---------------- LayerNorm -> bf16 hi/lo ----------------
__global__ void ln_kernel(const float* __restrict__ x, const float* __restrict__ g,
                          const float* __restrict__ b, bf16* __restrict__ oh, bf16* __restrict__ ol) {
    int row = blockIdx.x;
    const float* xr = x + (size_t)row * CC;
    float s = 0.f, sq = 0.f;
    for (int c = threadIdx.x; c < CC; c += blockDim.x) { float v = xr[c]; s += v; sq += v * v; }
    __shared__ float rs[256], rq[256];
    rs[threadIdx.x] = s; rq[threadIdx.x] = sq; __syncthreads();
    for (int st = 128; st > 0; st >>= 1) {
        if (threadIdx.x < st) { rs[threadIdx.x] += rs[threadIdx.x + st]; rq[threadIdx.x] += rq[threadIdx.x + st]; }
        __syncthreads();
    }
    float mean = rs[0] / CC;
    float var  = rq[0] / CC - mean * mean;
    float rstd = rsqrtf(var + 1e-3f);
    for (int c = threadIdx.x; c < CC; c += blockDim.x) {
        float v = (xr[c] - mean) * rstd * g[c] + b[c];
        bf16 h, l; split_bf(v, h, l);
        oh[(size_t)row * CC + c] = h;
        ol[(size_t)row * CC + c] = l;
    }
}

// ---------------- transpose+convert ----------------
__global__ void cvtT_kernel(const float* __restrict__ in, bf16* __restrict__ oh,
                            bf16* __restrict__ ol, int R, int Cc) {
    __shared__ float t[32][33];
    int bx = blockIdx.x * 32, by = blockIdx.y * 32;
    int x = bx + threadIdx.x;
    for (int i = threadIdx.y; i < 32; i += 8)
        t[i][threadIdx.x] = in[(size_t)(by + i) * Cc + x];
    __syncthreads();
    int xo = by + threadIdx.x;
    for (int i = threadIdx.y; i < 32; i += 8) {
        float v = t[threadIdx.x][i];
        bf16 h, l; split_bf(v, h, l);
        oh[(size_t)(bx + i) * R + xo] = h;
        ol[(size_t)(bx + i) * R + xo] = l;
    }
}

// ---------------- positional features ----------------
__global__ void pos_kernel(bf16* __restrict__ oh, bf16* __restrict__ ol) {
    int row = blockIdx.x;
    int i   = threadIdx.x;
    float p  = (float)(row - (TT - 1));
    float ap = fabsf(p);
    float sg = (p > 0.f) ? 1.f : ((p < 0.f) ? -1.f : 0.f);

    double log2T = log(1536.0) / log(2.0);
    double hl    = exp2(3.0 + (double)i * (log2T - 3.0) / 31.0);
    float coef   = (float)(-0.6931471805599453 / hl);
    float fe     = expf(coef * ap);

    float width = (float)(exp2((double)(i + 1)) - 1.0);
    float fcm   = (width > ap) ? 1.f : 0.f;

    double mean = 48.0 * (double)(i + 1);
    double stdv = 24.0;
    float conc  = (float)((mean / stdv) * (mean / stdv));
    float rate  = (float)(mean / (stdv * stdv));
    double lu   = (double)(conc - 1.f) * log((double)ap) - (double)rate * (double)ap;
    double lnn  = lgamma((double)conc) - (double)conc * log((double)rate);
    float prob  = (float)exp(lu - lnn) + 1e-8f;

    float mx = prob;
#pragma unroll
    for (int o = 16; o > 0; o >>= 1) mx = fmaxf(mx, __shfl_xor_sync(0xffffffffu, mx, o));
    float fg = prob / mx;

    float vals[6] = { fe, fcm, fg, sg * fe, sg * fcm, sg * fg };
    size_t base = (size_t)row * FF;
#pragma unroll
    for (int c = 0; c < 6; c++) {
        bf16 h, l; split_bf(vals[c], h, l);
        oh[base + c * 32 + i] = h;
        ol[base + c * 32 + i] = l;
    }
}

// ---------------- fused shift + softmax -> attn bf16 hi/lo ----------------
__global__ void softmax_merge_kernel(const float* __restrict__ cont, const float* __restrict__ rel,
                                     bf16* __restrict__ ah, bf16* __restrict__ al) {
    int row = blockIdx.x;
    int q = row % TT;
    const float* cr = cont + (size_t)row * TT;
    const float* rr = rel + (size_t)row * LLP + (TT - 1 - q);
    __shared__ float red[512];
    __shared__ float ebuf[TT];
    int t = threadIdx.x;
    float m = -1e30f;
    for (int j4 = t; j4 < TT / 4; j4 += 512) {
        float4 c4 = *(const float4*)(cr + j4 * 4);
        float s0 = c4.x + rr[j4 * 4 + 0];
        float s1 = c4.y + rr[j4 * 4 + 1];
        float s2 = c4.z + rr[j4 * 4 + 2];
        float s3 = c4.w + rr[j4 * 4 + 3];
        ebuf[j4 * 4 + 0] = s0; ebuf[j4 * 4 + 1] = s1;
        ebuf[j4 * 4 + 2] = s2; ebuf[j4 * 4 + 3] = s3;
        m = fmaxf(m, fmaxf(fmaxf(s0, s1), fmaxf(s2, s3)));
    }
    red[t] = m; __syncthreads();
    for (int st = 256; st > 0; st >>= 1) {
        if (t < st) red[t] = fmaxf(red[t], red[t + st]);
        __syncthreads();
    }
    m = red[0]; __syncthreads();
    float s = 0.f;
    for (int j = t; j < TT; j += 512) {
        float e = expf(ebuf[j] - m);
        ebuf[j] = e; s += e;
    }
    red[t] = s; __syncthreads();
    for (int st = 256; st > 0; st >>= 1) {
        if (t < st) red[t] += red[t + st];
        __syncthreads();
    }
    float inv = 1.f / red[0];
    for (int j2 = t; j2 < TT / 2; j2 += 512) {
        float v0 = ebuf[j2 * 2] * inv, v1 = ebuf[j2 * 2 + 1] * inv;
        *(uint32_t*)(ah + (size_t)row * TT + j2 * 2) = pack_bf2(v0, v1);
        *(uint32_t*)(al + (size_t)row * TT + j2 * 2) =
            pack_bf2(v0 - bfr(v0), v1 - bfr(v1));
    }
}

// ---------------- host launch ----------------
extern "C" void kernel_launch(void* const* d_in, const int* in_sizes, int n_in,
                              void* d_out, int out_size) {
    const float* x     = (const float*)d_in[0];
    const float* ln1_g = (const float*)d_in[1];
    const float* ln1_b = (const float*)d_in[2];
    const float* ln2_g = (const float*)d_in[3];
    const float* ln2_b = (const float*)d_in[4];
    const float* Wq    = (const float*)d_in[5];
    const float* Wk    = (const float*)d_in[6];
    const float* Wv    = (const float*)d_in[7];
    const float* Wr    = (const float*)d_in[8];
    const float* Wo    = (const float*)d_in[9];
    const float* bo    = (const float*)d_in[10];
    const float* rwb   = (const float*)d_in[11];
    const float* rrb   = (const float*)d_in[12];
    const float* W1    = (const float*)d_in[13];
    const float* b1    = (const float*)d_in[14];
    const float* W2    = (const float*)d_in[15];
    const float* b2    = (const float*)d_in[16];
    float* out = (float*)d_out;

#define GA(sym, ty) ({ void* p_; cudaGetSymbolAddress(&p_, sym); (ty*)p_; })
    bf16 *xnh = GA(g_xn_h, bf16), *xnl = GA(g_xn_l, bf16);
    bf16 *wqh = GA(g_wq_h, bf16), *wql = GA(g_wq_l, bf16);
    bf16 *wkh = GA(g_wk_h, bf16), *wkl = GA(g_wk_l, bf16);
    bf16 *wvh = GA(g_wv_h, bf16), *wvl = GA(g_wv_l, bf16);
    bf16 *wrh = GA(g_wr_h, bf16), *wrl = GA(g_wr_l, bf16);
    bf16 *woh = GA(g_wo_h, bf16), *wol = GA(g_wo_l, bf16);
    bf16 *w1h = GA(g_w1_h, bf16), *w1l = GA(g_w1_l, bf16);
    bf16 *w2h = GA(g_w2_h, bf16), *w2l = GA(g_w2_l, bf16);
    bf16 *qwh = GA(g_qw_h, bf16), *qwl = GA(g_qw_l, bf16);
    bf16 *qrh = GA(g_qr_h, bf16), *qrl = GA(g_qr_l, bf16);
    bf16 *kh  = GA(g_k_h, bf16),  *kl  = GA(g_k_l, bf16);
    float *vf = GA(g_vf, float);
    bf16 *vTh = GA(g_vT_h, bf16), *vTl = GA(g_vT_l, bf16);
    bf16 *ph  = GA(g_pos_h, bf16),*pl  = GA(g_pos_l, bf16);
    bf16 *rkh = GA(g_rk_h, bf16), *rkl = GA(g_rk_l, bf16);
    float *cont = GA(g_cont, float);
    float *rel  = GA(g_rel, float);
    bf16 *ath = GA(g_at_h, bf16), *atl = GA(g_at_l, bf16);
    bf16 *oh  = GA(g_o_h, bf16),  *ol  = GA(g_o_l, bf16);
    float *y  = GA(g_y, float);
    bf16 *ynh = GA(g_yn_h, bf16), *ynl = GA(g_yn_l, bf16);
    bf16 *h1h = GA(g_h1_h, bf16), *h1l = GA(g_h1_l, bf16);
    float *pp = GA(g_part, float);
#undef GA

    cudaFuncSetAttribute(tgemm128_kernel, cudaFuncAttributeMaxDynamicSharedMemorySize, T128_SM);
    cudaFuncSetAttribute(tgemm64_kernel,  cudaFuncAttributeMaxDynamicSharedMemorySize, T64_SM);
    dim3 tb(32, 8);
    const int KH = CC / 2;
    const int NB_CC  = (TT*CC/4 + 255)/256;
    const int NB_QK  = (TT*QKC/4 + 255)/256;

    // launch idx 3 = V split-K tgemm128 (PROFILED)
    ln_kernel<<<TT, 256>>>(x, ln1_g, ln1_b, xnh, xnl);                       // 0
    cvtT_kernel<<<dim3(CC/32, CC/32), tb>>>(Wv, wvh, wvl, CC, CC);           // 1
    pos_kernel<<<LLP, 32>>>(ph, pl);                                         // 2
    // 3: V projection, split-K x2
    tgemm128_kernel<<<dim3(CC/128, TT/128, 2), 128, T128_SM>>>(
        TT, CC, KH, xnh, xnl, CC, KH, wvh, wvl, CC, KH,
        pp, nullptr, nullptr, CC, (long long)TT*CC,
        nullptr, nullptr, 0, 0, 1.0f, 0, 0);
    combine_kernel<<<NB_CC, 256>>>(pp, TT*CC, CC, nullptr, nullptr, vf,
                                   nullptr, nullptr, nullptr, nullptr, nullptr);

    cvtT_kernel<<<dim3(QKC/32, CC/32), tb>>>(Wq, wqh, wql, CC, QKC);
    cvtT_kernel<<<dim3(QKC/32, CC/32), tb>>>(Wk, wkh, wkl, CC, QKC);
    cvtT_kernel<<<dim3(QKC/32, FF/32), tb>>>(Wr, wrh, wrl, FF, QKC);
    cvtT_kernel<<<dim3(CC/32, CC/32), tb>>>(Wo, woh, wol, CC, CC);
    cvtT_kernel<<<dim3(2*CC/32, CC/32), tb>>>(W1, w1h, w1l, CC, 2*CC);
    cvtT_kernel<<<dim3(CC/32, 2*CC/32), tb>>>(W2, w2h, w2l, 2*CC, CC);
    cvtT_kernel<<<dim3(CC/32, TT/32), tb>>>(vf, vTh, vTl, TT, CC);

    // q: split-K x2, combine with dual bias split
    tgemm64_kernel<<<dim3(QKC/64, TT/128, 2), 256, T64_SM>>>(
        TT, QKC, KH, xnh, xnl, CC, KH, wqh, wql, CC, KH,
        pp, nullptr, nullptr, QKC, (long long)TT*QKC, 0.125f);
    combine_kernel<<<NB_QK, 256>>>(pp, TT*QKC, QKC, rwb, nullptr, nullptr,
                                   qwh, qwl, rrb, qrh, qrl);

    // k: split-K x2
    tgemm64_kernel<<<dim3(QKC/64, TT/128, 2), 256, T64_SM>>>(
        TT, QKC, KH, xnh, xnl, CC, KH, wkh, wkl, CC, KH,
        pp, nullptr, nullptr, QKC, (long long)TT*QKC, 1.0f);
    combine_kernel<<<NB_QK, 256>>>(pp, TT*QKC, QKC, nullptr, nullptr, nullptr,
                                   kh, kl, nullptr, nullptr, nullptr);

    // r_k projection
    tgemm64_kernel<<<dim3(QKC/64, LLP/128, 1), 256, T64_SM>>>(
        LLP, QKC, FF, ph, pl, FF, 0, wrh, wrl, FF, 0,
        nullptr, rkh, rkl, QKC, 0, 1.0f);

    // content & rel logits [tile128]
    tgemm128_kernel<<<dim3(TT/128, TT/128, HH), 128, T128_SM>>>(
        TT, TT, HK, qwh, qwl, QKC, HK, kh, kl, QKC, HK,
        cont, nullptr, nullptr, TT, (long long)TT*TT,
        nullptr, nullptr, 0, 0, 1.0f, 0, 0);
    tgemm128_kernel<<<dim3(13, TT/128, HH), 128, T128_SM>>>(
        TT, LLP, HK, qrh, qrl, QKC, HK, rkh, rkl, QKC, HK,
        rel, nullptr, nullptr, LLP, (long long)TT*LLP,
        nullptr, nullptr, 0, 0, 1.0f, 0, 1);

    // shift + softmax
    softmax_merge_kernel<<<HH*TT, 512>>>(cont, rel, ath, atl);

    // attn @ V [tile64]
    tgemm64_kernel<<<dim3(3, TT/128, HH), 256, T64_SM>>>(
        TT, HV, TT, ath, atl, TT, (long long)TT*TT, vTh, vTl, TT, (long long)HV*TT,
        nullptr, oh, ol, CC, HV, 1.0f);

    // O projection: split-K x2 + combine (bias bo + residual x)
    tgemm128_kernel<<<dim3(CC/128, TT/128, 2), 128, T128_SM>>>(
        TT, CC, KH, oh, ol, CC, KH, woh, wol, CC, KH,
        pp, nullptr, nullptr, CC, (long long)TT*CC,
        nullptr, nullptr, 0, 0, 1.0f, 0, 0);
    combine_kernel<<<NB_CC, 256>>>(pp, TT*CC, CC, bo, x, y,
                                   nullptr, nullptr, nullptr, nullptr, nullptr);

    // LN2 + MLP
    ln_kernel<<<TT, 256>>>(y, ln2_g, ln2_b, ynh, ynl);
    tgemm128_kernel<<<dim3(2*CC/128, TT/128, 1), 128, T128_SM>>>(
        TT, 2*CC, CC, ynh, ynl, CC, 0, w1h, w1l, CC, 0,
        nullptr, h1h, h1l, 2*CC, 0, b1, nullptr, 0, 0, 1.0f, 1, 0);
    tgemm128_kernel<<<dim3(CC/128, TT/128, 2), 128, T128_SM>>>(
        TT, CC, CC, h1h, h1l, 2*CC, CC, w2h, w2l, 2*CC, CC,
        pp, nullptr, nullptr, CC, (long long)TT*CC,
        nullptr, nullptr, 0, 0, 1.0f, 0, 0);
    combine_kernel<<<NB_CC, 256>>>(pp, TT*CC, CC, b2, y, out,
                                   nullptr, nullptr, nullptr, nullptr, nullptr);
}

// round 15
// speedup vs baseline: 1.3255x; 1.3255x over previous
#include <cuda_runtime.h>
#include <cuda_bf16.h>
#include <cuda_fp16.h>
#include <math.h>
#include <stdint.h>

#define TT 1536
#define CC 1536
#define HH 8
#define HK 64
#define HV 192
#define FF 192
#define QKC 512
#define LLP 3072
typedef __nv_bfloat16 bf16;

// ---------------- scratch ----------------
__device__ bf16 g_xn_h[TT*CC],  g_xn_l[TT*CC];
__device__ bf16 g_wq_h[QKC*CC], g_wq_l[QKC*CC];
__device__ bf16 g_wk_h[QKC*CC], g_wk_l[QKC*CC];
__device__ bf16 g_wv_h[CC*CC],  g_wv_l[CC*CC];
__device__ bf16 g_wr_h[QKC*FF], g_wr_l[QKC*FF];
__device__ bf16 g_wo_h[CC*CC],  g_wo_l[CC*CC];
__device__ bf16 g_w1_h[2*CC*CC],g_w1_l[2*CC*CC];
__device__ bf16 g_w2_h[CC*2*CC],g_w2_l[CC*2*CC];
__device__ bf16 g_qw_h[TT*QKC], g_qw_l[TT*QKC];
__device__ bf16 g_qr_h[TT*QKC], g_qr_l[TT*QKC];
__device__ bf16 g_k_h[TT*QKC],  g_k_l[TT*QKC];
__device__ float g_vf[TT*CC];
__device__ bf16 g_vT_h[CC*TT],  g_vT_l[CC*TT];
__device__ bf16 g_pos_h[LLP*FF],g_pos_l[LLP*FF];
__device__ bf16 g_rk_h[LLP*QKC],g_rk_l[LLP*QKC];
__device__ __half g_cont[HH*TT*TT];             // fp16 logits
__device__ __half g_rel[(size_t)HH*TT*LLP];     // fp16 rel logits
__device__ bf16 g_at_h[HH*TT*TT], g_at_l[HH*TT*TT];
__device__ bf16 g_o_h[TT*CC],   g_o_l[TT*CC];
__device__ float g_y[TT*CC];
__device__ bf16 g_yn_h[TT*CC],  g_yn_l[TT*CC];
__device__ bf16 g_h1_h[TT*2*CC],g_h1_l[TT*2*CC];
__device__ float g_part[2*TT*CC];     // split-K partials

// ---------------- helpers ----------------
__device__ __forceinline__ uint32_t smem_u32(const void* p) {
    uint32_t a;
    asm("{ .reg .u64 t; cvta.to.shared.u64 t, %1; cvt.u32.u64 %0, t; }" : "=r"(a) : "l"(p));
    return a;
}
__device__ __forceinline__ void mma_bf16(float* c, const uint32_t* a, const uint32_t* b) {
    asm volatile("mma.sync.aligned.m16n8k16.row.col.f32.bf16.bf16.f32 "
        "{%0,%1,%2,%3},{%4,%5,%6,%7},{%8,%9},{%0,%1,%2,%3};"
        : "+f"(c[0]), "+f"(c[1]), "+f"(c[2]), "+f"(c[3])
        : "r"(a[0]), "r"(a[1]), "r"(a[2]), "r"(a[3]), "r"(b[0]), "r"(b[1]));
}
__device__ __forceinline__ void ldsm4(uint32_t* r, uint32_t addr) {
    asm volatile("ldmatrix.sync.aligned.m8n8.x4.shared.b16 {%0,%1,%2,%3}, [%4];"
        : "=r"(r[0]), "=r"(r[1]), "=r"(r[2]), "=r"(r[3]) : "r"(addr));
}
__device__ __forceinline__ void cpasync16(uint32_t dst, const void* src, uint32_t sz) {
    asm volatile("cp.async.ca.shared.global [%0], [%1], 16, %2;"
                 :: "r"(dst), "l"(src), "r"(sz) : "memory");
}
__device__ __forceinline__ void cp_commit() { asm volatile("cp.async.commit_group;" ::: "memory"); }
__device__ __forceinline__ void cp_wait0()  { asm volatile("cp.async.wait_group 0;" ::: "memory"); }
__device__ __forceinline__ uint32_t pack_bf2(float a, float b) {
    __nv_bfloat162 t = __floats2bfloat162_rn(a, b);
    return *reinterpret_cast<uint32_t*>(&t);
}
__device__ __forceinline__ uint32_t pack_hf2(float a, float b) {
    __half2 t = __floats2half2_rn(a, b);
    return *reinterpret_cast<uint32_t*>(&t);
}
__device__ __forceinline__ float bfr(float x) { return __bfloat162float(__float2bfloat16(x)); }
__device__ __forceinline__ void split_bf(float v, bf16& h, bf16& l) {
    h = __float2bfloat16(v);
    l = __float2bfloat16(v - __bfloat162float(h));
}

// ================= tile 128x128 GEMM (R11 geometry: 256 thr, warp 64x32) =================
#define R128 80
#define T128_AH 0
#define T128_AL 10240
#define T128_BH 20480
#define T128_BL 30720
#define T128_STG 40960
#define T128_SM (2*T128_STG)

__global__ __launch_bounds__(256, 2)
void tgemm128_kernel(int M, int N, int K,
                  const bf16* __restrict__ Ah, const bf16* __restrict__ Al, int lda, long long sA,
                  const bf16* __restrict__ Bh, const bf16* __restrict__ Bl, int ldb, long long sB,
                  float* __restrict__ Cf, bf16* __restrict__ Ch, bf16* __restrict__ Cl,
                  __half* __restrict__ Cq,
                  int ldc, long long sC,
                  const float* __restrict__ bias,
                  const float* __restrict__ Rp, int ldr, long long sR,
                  float alpha, int relu, int win)
{
    extern __shared__ char smem[];
    uint32_t sbase = smem_u32(smem);
    int tid = threadIdx.x, wid = tid >> 5, lane = tid & 31;
    int grp = lane >> 2, tig = lane & 3;
    int wm = wid & 1, wn = wid >> 1;
    int z = blockIdx.z;
    Ah += (long long)z * sA;  Al += (long long)z * sA;
    Bh += (long long)z * sB;  Bl += (long long)z * sB;
    const float* Rb = Rp ? Rp + (long long)z * sR : nullptr;
    int bm = blockIdx.y * 128;
    int bn = win ? (11 - blockIdx.y + blockIdx.x) * 128 : blockIdx.x * 128;

    const int nch = K >> 5;
    const int sr = tid >> 1, ss = tid & 1;
    const uint32_t sdst = sr * R128 + ss * 32;
    const bf16* gAh = Ah + (size_t)(bm + sr) * lda + ss * 16;
    const bf16* gAl = Al + (size_t)(bm + sr) * lda + ss * 16;
    const bf16* gBh = Bh + (size_t)(bn + sr) * ldb + ss * 16;
    const bf16* gBl = Bl + (size_t)(bn + sr) * ldb + ss * 16;

    const uint32_t lA = (uint32_t)(lane & 15) * R128 + (uint32_t)(lane >> 4) * 16;
    const uint32_t lB = ((uint32_t)((lane >> 4) * 8 + (lane & 7))) * R128 + (uint32_t)((lane >> 3) & 1) * 16;

    float acc[4][4][4];
#pragma unroll
    for (int a = 0; a < 4; a++)
#pragma unroll
        for (int b = 0; b < 4; b++)
#pragma unroll
            for (int r = 0; r < 4; r++) acc[a][b][r] = 0.f;

    {
        uint32_t st = sbase + sdst;
        cpasync16(st + T128_AH,      gAh,     16);
        cpasync16(st + T128_AH + 16, gAh + 8, 16);
        cpasync16(st + T128_AL,      gAl,     16);
        cpasync16(st + T128_AL + 16, gAl + 8, 16);
        cpasync16(st + T128_BH,      gBh,     16);
        cpasync16(st + T128_BH + 16, gBh + 8, 16);
        cpasync16(st + T128_BL,      gBl,     16);
        cpasync16(st + T128_BL + 16, gBl + 8, 16);
        cp_commit();
    }

    for (int c = 0; c < nch; c++) {
        cp_wait0();
        __syncthreads();

        if (c + 1 < nch) {
            uint32_t st = sbase + ((c + 1) & 1) * T128_STG + sdst;
            int k0 = (c + 1) << 5;
            cpasync16(st + T128_AH,      gAh + k0,     16);
            cpasync16(st + T128_AH + 16, gAh + k0 + 8, 16);
            cpasync16(st + T128_AL,      gAl + k0,     16);
            cpasync16(st + T128_AL + 16, gAl + k0 + 8, 16);
            cpasync16(st + T128_BH,      gBh + k0,     16);
            cpasync16(st + T128_BH + 16, gBh + k0 + 8, 16);
            cpasync16(st + T128_BL,      gBl + k0,     16);
            cpasync16(st + T128_BL + 16, gBl + k0 + 8, 16);
        }
        cp_commit();

        uint32_t stg = sbase + (c & 1) * T128_STG;
#pragma unroll
        for (int ks = 0; ks < 2; ks++) {
            uint32_t koff = (uint32_t)ks * 32;
            uint32_t bh[2][4], bl[2][4];
#pragma unroll
            for (int p = 0; p < 2; p++) {
                uint32_t ba = stg + (uint32_t)(wn * 32 + p * 16) * R128 + koff + lB;
                ldsm4(bh[p], ba + T128_BH);
                ldsm4(bl[p], ba + T128_BL);
            }
#pragma unroll
            for (int ms = 0; ms < 4; ms++) {
                uint32_t aa = stg + (uint32_t)(wm * 64 + ms * 16) * R128 + koff + lA;
                uint32_t ah[4], al[4];
                ldsm4(ah, aa + T128_AH);
                ldsm4(al, aa + T128_AL);
#pragma unroll
                for (int ns = 0; ns < 4; ns++) {
                    uint32_t* bhp = &bh[ns >> 1][(ns & 1) * 2];
                    uint32_t* blp = &bl[ns >> 1][(ns & 1) * 2];
                    mma_bf16(acc[ms][ns], ah, bhp);
                    mma_bf16(acc[ms][ns], ah, blp);
                    mma_bf16(acc[ms][ns], al, bhp);
                }
            }
        }
    }

    Cf  = Cf  ? Cf  + (long long)z * sC : nullptr;
    Ch  = Ch  ? Ch  + (long long)z * sC : nullptr;
    Cl  = Cl  ? Cl  + (long long)z * sC : nullptr;
    Cq  = Cq  ? Cq  + (long long)z * sC : nullptr;
    const bool has_bias = (bias != nullptr);
#pragma unroll
    for (int ms = 0; ms < 4; ms++) {
        int row0 = bm + wm * 64 + ms * 16 + grp;
#pragma unroll
        for (int ns = 0; ns < 4; ns++) {
            int col = bn + wn * 32 + ns * 8 + (tig << 1);
#pragma unroll
            for (int h = 0; h < 2; h++) {
                int m = row0 + h * 8;
                float v0 = alpha * acc[ms][ns][h * 2 + 0];
                float v1 = alpha * acc[ms][ns][h * 2 + 1];
                if (has_bias) { v0 += bias[col]; v1 += bias[col + 1]; }
                if (relu) { v0 = fmaxf(v0, 0.f); v1 = fmaxf(v1, 0.f); }
                if (Cq) {
                    *(uint32_t*)(Cq + (size_t)m * ldc + col) = pack_hf2(v0, v1);
                } else if (Cf) {
                    if (Rb) {
                        const float* rp = Rb + (size_t)m * ldr + col;
                        v0 += rp[0]; v1 += rp[1];
                    }
                    *(float2*)(Cf + (size_t)m * ldc + col) = make_float2(v0, v1);
                } else {
                    *(uint32_t*)(Ch + (size_t)m * ldc + col) = pack_bf2(v0, v1);
                    *(uint32_t*)(Cl + (size_t)m * ldc + col) =
                        pack_bf2(v0 - bfr(v0), v1 - bfr(v1));
                }
            }
        }
    }
}

// ================= tile 128x64 GEMM (small-N) =================
#define R64 80
#define T64_AH 0
#define T64_AL 10240
#define T64_BH 20480
#define T64_BL 25600
#define T64_STG 30720
#define T64_SM (2*T64_STG)

__global__ __launch_bounds__(256, 2)
void tgemm64_kernel(int M, int N, int K,
                  const bf16* __restrict__ Ah, const bf16* __restrict__ Al, int lda, long long sA,
                  const bf16* __restrict__ Bh, const bf16* __restrict__ Bl, int ldb, long long sB,
                  float* __restrict__ Cf, bf16* __restrict__ Ch, bf16* __restrict__ Cl,
                  int ldc, long long sC, float alpha)
{
    extern __shared__ char smem[];
    uint32_t sbase = smem_u32(smem);
    int tid = threadIdx.x, wid = tid >> 5, lane = tid & 31;
    int grp = lane >> 2, tig = lane & 3;
    int wm = wid & 3, wn = wid >> 2;
    int z = blockIdx.z;
    Ah += (long long)z * sA;  Al += (long long)z * sA;
    Bh += (long long)z * sB;  Bl += (long long)z * sB;
    int bm = blockIdx.y * 128;
    int bn = blockIdx.x * 64;

    const int nch = K >> 5;
    const int sra = tid >> 1, ssa = tid & 1;
    const int srb = tid >> 2, ssb = tid & 3;
    const uint32_t dstA = sra * R64 + ssa * 32;
    const uint32_t dstB = srb * R64 + ssb * 16;

    const bf16* gAh = Ah + (size_t)(bm + sra) * lda + ssa * 16;
    const bf16* gAl = Al + (size_t)(bm + sra) * lda + ssa * 16;
    const bf16* gBh = Bh + (size_t)(bn + srb) * ldb + ssb * 8;
    const bf16* gBl = Bl + (size_t)(bn + srb) * ldb + ssb * 8;

    const uint32_t lA = (uint32_t)(lane & 15) * R64 + (uint32_t)(lane >> 4) * 16;
    const uint32_t lB = ((uint32_t)((lane >> 4) * 8 + (lane & 7))) * R64 + (uint32_t)((lane >> 3) & 1) * 16;

    float acc[2][4][4];
#pragma unroll
    for (int a = 0; a < 2; a++)
#pragma unroll
        for (int b = 0; b < 4; b++)
#pragma unroll
            for (int r = 0; r < 4; r++) acc[a][b][r] = 0.f;

    {
        uint32_t st = sbase;
        cpasync16(st + T64_AH + dstA,      gAh,     16);
        cpasync16(st + T64_AH + dstA + 16, gAh + 8, 16);
        cpasync16(st + T64_AL + dstA,      gAl,     16);
        cpasync16(st + T64_AL + dstA + 16, gAl + 8, 16);
        cpasync16(st + T64_BH + dstB,      gBh,     16);
        cpasync16(st + T64_BL + dstB,      gBl,     16);
        cp_commit();
    }

    for (int c = 0; c < nch; c++) {
        cp_wait0();
        __syncthreads();

        if (c + 1 < nch) {
            uint32_t st = sbase + ((c + 1) & 1) * T64_STG;
            int k0 = (c + 1) << 5;
            cpasync16(st + T64_AH + dstA,      gAh + k0,     16);
            cpasync16(st + T64_AH + dstA + 16, gAh + k0 + 8, 16);
            cpasync16(st + T64_AL + dstA,      gAl + k0,     16);
            cpasync16(st + T64_AL + dstA + 16, gAl + k0 + 8, 16);
            cpasync16(st + T64_BH + dstB,      gBh + k0,     16);
            cpasync16(st + T64_BL + dstB,      gBl + k0,     16);
        }
        cp_commit();

        uint32_t stg = sbase + (c & 1) * T64_STG;
#pragma unroll
        for (int ks = 0; ks < 2; ks++) {
            uint32_t koff = (uint32_t)ks * 32;
            uint32_t bh[2][4], bl[2][4];
#pragma unroll
            for (int p = 0; p < 2; p++) {
                uint32_t ba = stg + (uint32_t)(wn * 32 + p * 16) * R64 + koff + lB;
                ldsm4(bh[p], ba + T64_BH);
                ldsm4(bl[p], ba + T64_BL);
            }
#pragma unroll
            for (int ms = 0; ms < 2; ms++) {
                uint32_t aa = stg + (uint32_t)(wm * 32 + ms * 16) * R64 + koff + lA;
                uint32_t ah[4], al[4];
                ldsm4(ah, aa + T64_AH);
                ldsm4(al, aa + T64_AL);
#pragma unroll
                for (int ns = 0; ns < 4; ns++) {
                    uint32_t* bhp = &bh[ns >> 1][(ns & 1) * 2];
                    uint32_t* blp = &bl[ns >> 1][(ns & 1) * 2];
                    mma_bf16(acc[ms][ns], ah, bhp);
                    mma_bf16(acc[ms][ns], ah, blp);
                    mma_bf16(acc[ms][ns], al, bhp);
                }
            }
        }
    }

    Cf  = Cf  ? Cf  + (long long)z * sC : nullptr;
    Ch  = Ch  ? Ch  + (long long)z * sC : nullptr;
    Cl  = Cl  ? Cl  + (long long)z * sC : nullptr;
#pragma unroll
    for (int ms = 0; ms < 2; ms++) {
        int row0 = bm + wm * 32 + ms * 16 + grp;
#pragma unroll
        for (int ns = 0; ns < 4; ns++) {
            int col = bn + wn * 32 + ns * 8 + (tig << 1);
#pragma unroll
            for (int h = 0; h < 2; h++) {
                int m = row0 + h * 8;
                float v0 = alpha * acc[ms][ns][h * 2 + 0];
                float v1 = alpha * acc[ms][ns][h * 2 + 1];
                if (Cf) {
                    *(float2*)(Cf + (size_t)m * ldc + col) = make_float2(v0, v1);
                } else {
                    *(uint32_t*)(Ch + (size_t)m * ldc + col) = pack_bf2(v0, v1);
                    *(uint32_t*)(Cl + (size_t)m * ldc + col) =
                        pack_bf2(v0 - bfr(v0), v1 - bfr(v1));
                }
            }
        }
    }
}

// ---------------- split-K combine ----------------
__global__ void combine_kernel(const float* __restrict__ p, int n, int ld,
                               const float* __restrict__ bias, const float* __restrict__ res,
                               float* __restrict__ outf,
                               bf16* __restrict__ oh, bf16* __restrict__ ol,
                               const float* __restrict__ bias2,
                               bf16* __restrict__ oh2, bf16* __restrict__ ol2)
{
    int i4 = blockIdx.x * 256 + threadIdx.x;
    if (i4 * 4 >= n) return;
    int i = i4 * 4;
    float4 a = *(const float4*)(p + i);
    float4 b = *(const float4*)(p + n + i);
    float4 s = make_float4(a.x + b.x, a.y + b.y, a.z + b.z, a.w + b.w);
    int col = i % ld;
    float4 v = s;
    if (bias) {
        float4 bb = *(const float4*)(bias + col);
        v.x += bb.x; v.y += bb.y; v.z += bb.z; v.w += bb.w;
    }
    if (res) {
        float4 r = *(const float4*)(res + i);
        v.x += r.x; v.y += r.y; v.z += r.z; v.w += r.w;
    }
    if (outf) {
        *(float4*)(outf + i) = v;
    } else {
        *(uint32_t*)(oh + i)     = pack_bf2(v.x, v.y);
        *(uint32_t*)(oh + i + 2) = pack_bf2(v.z, v.w);
        *(uint32_t*)(ol + i)     = pack_bf2(v.x - bfr(v.x), v.y - bfr(v.y));
        *(uint32_t*)(ol + i + 2) = pack_bf2(v.z - bfr(v.z), v.w - bfr(v.w));
        if (oh2) {
            float4 b2v = *(const float4*)(bias2 + col);
            float4 u = make_float4(s.x + b2v.x, s.y + b2v.y, s.z + b2v.z, s.w + b2v.w);
            *(uint32_t*)(oh2 + i)     = pack_bf2(u.x, u.y);
            *(uint32_t*)(oh2 + i + 2) = pack_bf2(u.z, u.w);
            *(uint32_t*)(ol2 + i)     = pack_bf2(u.x - bfr(u.x), u.y - bfr(u.y));
            *(uint32_t*)(ol2 + i + 2) = pack_bf2(u.z - bfr(u.z), u.w - bfr(u.w));
        }
    }
}

// ---------------- LayerNorm -> bf16 hi/lo ----------------
__global__ void ln_kernel(const float* __restrict__ x, const float* __restrict__ g,
                          const float* __restrict__ b, bf16* __restrict__ oh, bf16* __restrict__ ol) {
    int row = blockIdx.x;
    const float* xr = x + (size_t)row * CC;
    float s = 0.f, sq = 0.f;
    for (int c = threadIdx.x; c < CC; c += blockDim.x) { float v = xr[c]; s += v; sq += v * v; }
    __shared__ float rs[256], rq[256];
    rs[threadIdx.x] = s; rq[threadIdx.x] = sq; __syncthreads();
    for (int st = 128; st > 0; st >>= 1) {
        if (threadIdx.x < st) { rs[threadIdx.x] += rs[threadIdx.x + st]; rq[threadIdx.x] += rq[threadIdx.x + st]; }
        __syncthreads();
    }
    float mean = rs[0] / CC;
    float var  = rq[0] / CC - mean * mean;
    float rstd = rsqrtf(var + 1e-3f);
    for (int c = threadIdx.x; c < CC; c += blockDim.x) {
        float v = (xr[c] - mean) * rstd * g[c] + b[c];
        bf16 h, l; split_bf(v, h, l);
        oh[(size_t)row * CC + c] = h;
        ol[(size_t)row * CC + c] = l;
    }
}

// ---------------- transpose+convert ----------------
__global__ void cvtT_kernel(const float* __restrict__ in, bf16* __restrict__ oh,
                            bf16* __restrict__ ol, int R, int Cc) {
    __shared__ float t[32][33];
    int bx = blockIdx.x * 32, by = blockIdx.y * 32;
    int x = bx + threadIdx.x;
    for (int i = threadIdx.y; i < 32; i += 8)
        t[i][threadIdx.x] = in[(size_t)(by + i) * Cc + x];
    __syncthreads();
    int xo = by + threadIdx.x;
    for (int i = threadIdx.y; i < 32; i += 8) {
        float v = t[threadIdx.x][i];
        bf16 h, l; split_bf(v, h, l);
        oh[(size_t)(bx + i) * R + xo] = h;
        ol[(size_t)(bx + i) * R + xo] = l;
    }
}

// ---------------- positional features ----------------
__global__ void pos_kernel(bf16* __restrict__ oh, bf16* __restrict__ ol) {
    int row = blockIdx.x;
    int i   = threadIdx.x;
    float p  = (float)(row - (TT - 1));
    float ap = fabsf(p);
    float sg = (p > 0.f) ? 1.f : ((p < 0.f) ? -1.f : 0.f);

    double log2T = log(1536.0) / log(2.0);
    double hl    = exp2(3.0 + (double)i * (log2T - 3.0) / 31.0);
    float coef   = (float)(-0.6931471805599453 / hl);
    float fe     = expf(coef * ap);

    float width = (float)(exp2((double)(i + 1)) - 1.0);
    float fcm   = (width > ap) ? 1.f : 0.f;

    double mean = 48.0 * (double)(i + 1);
    double stdv = 24.0;
    float conc  = (float)((mean / stdv) * (mean / stdv));
    float rate  = (float)(mean / (stdv * stdv));
    double lu   = (double)(conc - 1.f) * log((double)ap) - (double)rate * (double)ap;
    double lnn  = lgamma((double)conc) - (double)conc * log((double)rate);
    float prob  = (float)exp(lu - lnn) + 1e-8f;

    float mx = prob;
#pragma unroll
    for (int o = 16; o > 0; o >>= 1) mx = fmaxf(mx, __shfl_xor_sync(0xffffffffu, mx, o));
    float fg = prob / mx;

    float vals[6] = { fe, fcm, fg, sg * fe, sg * fcm, sg * fg };
    size_t base = (size_t)row * FF;
#pragma unroll
    for (int c = 0; c < 6; c++) {
        bf16 h, l; split_bf(vals[c], h, l);
        oh[base + c * 32 + i] = h;
        ol[base + c * 32 + i] = l;
    }
}

// ---------------- fused shift + softmax (fp16 logits) -> attn bf16 hi/lo ----------------
__global__ void softmax_merge_kernel(const __half* __restrict__ cont, const __half* __restrict__ rel,
                                     bf16* __restrict__ ah, bf16* __restrict__ al) {
    int row = blockIdx.x;
    int q = row % TT;
    const __half* cr = cont + (size_t)row * TT;
    const __half* rr = rel + (size_t)row * LLP + (TT - 1 - q);
    __shared__ float red[512];
    __shared__ float ebuf[TT];
    int t = threadIdx.x;
    float m = -1e30f;
    for (int j2 = t; j2 < TT / 2; j2 += 512) {
        float2 c2 = __half22float2(*(const __half2*)(cr + j2 * 2));
        float s0 = c2.x + __half2float(rr[j2 * 2 + 0]);
        float s1 = c2.y + __half2float(rr[j2 * 2 + 1]);
        ebuf[j2 * 2 + 0] = s0; ebuf[j2 * 2 + 1] = s1;
        m = fmaxf(m, fmaxf(s0, s1));
    }
    red[t] = m; __syncthreads();
    for (int st = 256; st > 0; st >>= 1) {
        if (t < st) red[t] = fmaxf(red[t], red[t + st]);
        __syncthreads();
    }
    m = red[0]; __syncthreads();
    float s = 0.f;
    for (int j = t; j < TT; j += 512) {
        float e = expf(ebuf[j] - m);
        ebuf[j] = e; s += e;
    }
    red[t] = s; __syncthreads();
    for (int st = 256; st > 0; st >>= 1) {
        if (t < st) red[t] += red[t + st];
        __syncthreads();
    }
    float inv = 1.f / red[0];
    for (int j2 = t; j2 < TT / 2; j2 += 512) {
        float v0 = ebuf[j2 * 2] * inv, v1 = ebuf[j2 * 2 + 1] * inv;
        *(uint32_t*)(ah + (size_t)row * TT + j2 * 2) = pack_bf2(v0, v1);
        *(uint32_t*)(al + (size_t)row * TT + j2 * 2) =
            pack_bf2(v0 - bfr(v0), v1 - bfr(v1));
    }
}

// ---------------- host launch ----------------
extern "C" void kernel_launch(void* const* d_in, const int* in_sizes, int n_in,
                              void* d_out, int out_size) {
    const float* x     = (const float*)d_in[0];
    const float* ln1_g = (const float*)d_in[1];
    const float* ln1_b = (const float*)d_in[2];
    const float* ln2_g = (const float*)d_in[3];
    const float* ln2_b = (const float*)d_in[4];
    const float* Wq    = (const float*)d_in[5];
    const float* Wk    = (const float*)d_in[6];
    const float* Wv    = (const float*)d_in[7];
    const float* Wr    = (const float*)d_in[8];
    const float* Wo    = (const float*)d_in[9];
    const float* bo    = (const float*)d_in[10];
    const float* rwb   = (const float*)d_in[11];
    const float* rrb   = (const float*)d_in[12];
    const float* W1    = (const float*)d_in[13];
    const float* b1    = (const float*)d_in[14];
    const float* W2    = (const float*)d_in[15];
    const float* b2    = (const float*)d_in[16];
    float* out = (float*)d_out;

#define GA(sym, ty) ({ void* p_; cudaGetSymbolAddress(&p_, sym); (ty*)p_; })
    bf16 *xnh = GA(g_xn_h, bf16), *xnl = GA(g_xn_l, bf16);
    bf16 *wqh = GA(g_wq_h, bf16), *wql = GA(g_wq_l, bf16);
    bf16 *wkh = GA(g_wk_h, bf16), *wkl = GA(g_wk_l, bf16);
    bf16 *wvh = GA(g_wv_h, bf16), *wvl = GA(g_wv_l, bf16);
    bf16 *wrh = GA(g_wr_h, bf16), *wrl = GA(g_wr_l, bf16);
    bf16 *woh = GA(g_wo_h, bf16), *wol = GA(g_wo_l, bf16);
    bf16 *w1h = GA(g_w1_h, bf16), *w1l = GA(g_w1_l, bf16);
    bf16 *w2h = GA(g_w2_h, bf16), *w2l = GA(g_w2_l, bf16);
    bf16 *qwh = GA(g_qw_h, bf16), *qwl = GA(g_qw_l, bf16);
    bf16 *qrh = GA(g_qr_h, bf16), *qrl = GA(g_qr_l, bf16);
    bf16 *kh  = GA(g_k_h, bf16),  *kl  = GA(g_k_l, bf16);
    float *vf = GA(g_vf, float);
    bf16 *vTh = GA(g_vT_h, bf16), *vTl = GA(g_vT_l, bf16);
    bf16 *ph  = GA(g_pos_h, bf16),*pl  = GA(g_pos_l, bf16);
    bf16 *rkh = GA(g_rk_h, bf16), *rkl = GA(g_rk_l, bf16);
    __half *cont = GA(g_cont, __half);
    __half *rel  = GA(g_rel, __half);
    bf16 *ath = GA(g_at_h, bf16), *atl = GA(g_at_l, bf16);
    bf16 *oh  = GA(g_o_h, bf16),  *ol  = GA(g_o_l, bf16);
    float *y  = GA(g_y, float);
    bf16 *ynh = GA(g_yn_h, bf16), *ynl = GA(g_yn_l, bf16);
    bf16 *h1h = GA(g_h1_h, bf16), *h1l = GA(g_h1_l, bf16);
    float *pp = GA(g_part, float);
#undef GA

    cudaFuncSetAttribute(tgemm128_kernel, cudaFuncAttributeMaxDynamicSharedMemorySize, T128_SM);
    cudaFuncSetAttribute(tgemm64_kernel,  cudaFuncAttributeMaxDynamicSharedMemorySize, T64_SM);
    dim3 tb(32, 8);
    const int KH = CC / 2;
    const int NB_CC  = (TT*CC/4 + 255)/256;
    const int NB_QK  = (TT*QKC/4 + 255)/256;

    // launch idx 3 = V split-K tgemm128 (PROFILED)
    ln_kernel<<<TT, 256>>>(x, ln1_g, ln1_b, xnh, xnl);                       // 0
    cvtT_kernel<<<dim3(CC/32, CC/32), tb>>>(Wv, wvh, wvl, CC, CC);           // 1
    pos_kernel<<<LLP, 32>>>(ph, pl);                                         // 2
    // 3: V projection, split-K x2
    tgemm128_kernel<<<dim3(CC/128, TT/128, 2), 256, T128_SM>>>(
        TT, CC, KH, xnh, xnl, CC, KH, wvh, wvl, CC, KH,
        pp, nullptr, nullptr, nullptr, CC, (long long)TT*CC,
        nullptr, nullptr, 0, 0, 1.0f, 0, 0);
    combine_kernel<<<NB_CC, 256>>>(pp, TT*CC, CC, nullptr, nullptr, vf,
                                   nullptr, nullptr, nullptr, nullptr, nullptr);

    cvtT_kernel<<<dim3(QKC/32, CC/32), tb>>>(Wq, wqh, wql, CC, QKC);
    cvtT_kernel<<<dim3(QKC/32, CC/32), tb>>>(Wk, wkh, wkl, CC, QKC);
    cvtT_kernel<<<dim3(QKC/32, FF/32), tb>>>(Wr, wrh, wrl, FF, QKC);
    cvtT_kernel<<<dim3(CC/32, CC/32), tb>>>(Wo, woh, wol, CC, CC);
    cvtT_kernel<<<dim3(2*CC/32, CC/32), tb>>>(W1, w1h, w1l, CC, 2*CC);
    cvtT_kernel<<<dim3(CC/32, 2*CC/32), tb>>>(W2, w2h, w2l, 2*CC, CC);
    cvtT_kernel<<<dim3(CC/32, TT/32), tb>>>(vf, vTh, vTl, TT, CC);

    // q: split-K x2, combine with dual bias split
    tgemm64_kernel<<<dim3(QKC/64, TT/128, 2), 256, T64_SM>>>(
        TT, QKC, KH, xnh, xnl, CC, KH, wqh, wql, CC, KH,
        pp, nullptr, nullptr, QKC, (long long)TT*QKC, 0.125f);
    combine_kernel<<<NB_QK, 256>>>(pp, TT*QKC, QKC, rwb, nullptr, nullptr,
                                   qwh, qwl, rrb, qrh, qrl);

    // k: split-K x2
    tgemm64_kernel<<<dim3(QKC/64, TT/128, 2), 256, T64_SM>>>(
        TT, QKC, KH, xnh, xnl, CC, KH, wkh, wkl, CC, KH,
        pp, nullptr, nullptr, QKC, (long long)TT*QKC, 1.0f);
    combine_kernel<<<NB_QK, 256>>>(pp, TT*QKC, QKC, nullptr, nullptr, nullptr,
                                   kh, kl, nullptr, nullptr, nullptr);

    // r_k projection
    tgemm64_kernel<<<dim3(QKC/64, LLP/128, 1), 256, T64_SM>>>(
        LLP, QKC, FF, ph, pl, FF, 0, wrh, wrl, FF, 0,
        nullptr, rkh, rkl, QKC, 0, 1.0f);

    // content & rel logits -> fp16
    tgemm128_kernel<<<dim3(TT/128, TT/128, HH), 256, T128_SM>>>(
        TT, TT, HK, qwh, qwl, QKC, HK, kh, kl, QKC, HK,
        nullptr, nullptr, nullptr, cont, TT, (long long)TT*TT,
        nullptr, nullptr, 0, 0, 1.0f, 0, 0);
    tgemm128_kernel<<<dim3(13, TT/128, HH), 256, T128_SM>>>(
        TT, LLP, HK, qrh, qrl, QKC, HK, rkh, rkl, QKC, HK,
        nullptr, nullptr, nullptr, rel, LLP, (long long)TT*LLP,
        nullptr, nullptr, 0, 0, 1.0f, 0, 1);

    // shift + softmax (fp16 in)
    softmax_merge_kernel<<<HH*TT, 512>>>(cont, rel, ath, atl);

    // attn @ V [tile64]
    tgemm64_kernel<<<dim3(3, TT/128, HH), 256, T64_SM>>>(
        TT, HV, TT, ath, atl, TT, (long long)TT*TT, vTh, vTl, TT, (long long)HV*TT,
        nullptr, oh, ol, CC, HV, 1.0f);

    // O projection: split-K x2 + combine (bias bo + residual x)
    tgemm128_kernel<<<dim3(CC/128, TT/128, 2), 256, T128_SM>>>(
        TT, CC, KH, oh, ol, CC, KH, woh, wol, CC, KH,
        pp, nullptr, nullptr, nullptr, CC, (long long)TT*CC,
        nullptr, nullptr, 0, 0, 1.0f, 0, 0);
    combine_kernel<<<NB_CC, 256>>>(pp, TT*CC, CC, bo, x, y,
                                   nullptr, nullptr, nullptr, nullptr, nullptr);

    // LN2 + MLP
    ln_kernel<<<TT, 256>>>(y, ln2_g, ln2_b, ynh, ynl);
    tgemm128_kernel<<<dim3(2*CC/128, TT/128, 1), 256, T128_SM>>>(
        TT, 2*CC, CC, ynh, ynl, CC, 0, w1h, w1l, CC, 0,
        nullptr, h1h, h1l, nullptr, 2*CC, 0, b1, nullptr, 0, 0, 1.0f, 1, 0);
    tgemm128_kernel<<<dim3(CC/128, TT/128, 2), 256, T128_SM>>>(
        TT, CC, CC, h1h, h1l, 2*CC, CC, w2h, w2l, 2*CC, CC,
        pp, nullptr, nullptr, nullptr, CC, (long long)TT*CC,
        nullptr, nullptr, 0, 0, 1.0f, 0, 0);
    combine_kernel<<<NB_CC, 256>>>(pp, TT*CC, CC, b2, y, out,
                                   nullptr, nullptr, nullptr, nullptr, nullptr);
}

// round 17
// speedup vs baseline: 1.3794x; 1.0406x over previous
#include <cuda_runtime.h>
#include <cuda_bf16.h>
#include <cuda_fp16.h>
#include <math.h>
#include <stdint.h>

#define TT 1536
#define CC 1536
#define HH 8
#define HK 64
#define HV 192
#define FF 192
#define QKC 512
#define LLP 3072
typedef __nv_bfloat16 bf16;

// ---------------- scratch ----------------
__device__ bf16 g_xn_h[TT*CC],  g_xn_l[TT*CC];
__device__ bf16 g_wq_h[QKC*CC], g_wq_l[QKC*CC];
__device__ bf16 g_wk_h[QKC*CC], g_wk_l[QKC*CC];
__device__ bf16 g_wv_h[CC*CC],  g_wv_l[CC*CC];
__device__ bf16 g_wr_h[QKC*FF], g_wr_l[QKC*FF];
__device__ bf16 g_wo_h[CC*CC],  g_wo_l[CC*CC];
__device__ bf16 g_w1_h[2*CC*CC],g_w1_l[2*CC*CC];
__device__ bf16 g_w2_h[CC*2*CC],g_w2_l[CC*2*CC];
__device__ bf16 g_qw_h[TT*QKC], g_qw_l[TT*QKC];
__device__ bf16 g_qr_h[TT*QKC], g_qr_l[TT*QKC];
__device__ bf16 g_k_h[TT*QKC],  g_k_l[TT*QKC];
__device__ bf16 g_vT_h[CC*TT],  g_vT_l[CC*TT];
__device__ bf16 g_pos_h[LLP*FF],g_pos_l[LLP*FF];
__device__ bf16 g_rk_h[LLP*QKC],g_rk_l[LLP*QKC];
__device__ __half g_cont[HH*TT*TT];
__device__ __half g_rel[(size_t)HH*TT*LLP];
__device__ bf16 g_at_h[HH*TT*TT], g_at_l[HH*TT*TT];
__device__ bf16 g_o_h[TT*CC],   g_o_l[TT*CC];
__device__ float g_y[TT*CC];
__device__ bf16 g_yn_h[TT*CC],  g_yn_l[TT*CC];
__device__ bf16 g_h1_h[TT*2*CC],g_h1_l[TT*2*CC];
__device__ float g_part[2*TT*CC];

// ---------------- helpers ----------------
__device__ __forceinline__ uint32_t smem_u32(const void* p) {
    uint32_t a;
    asm("{ .reg .u64 t; cvta.to.shared.u64 t, %1; cvt.u32.u64 %0, t; }" : "=r"(a) : "l"(p));
    return a;
}
__device__ __forceinline__ void mma_bf16(float* c, const uint32_t* a, const uint32_t* b) {
    asm volatile("mma.sync.aligned.m16n8k16.row.col.f32.bf16.bf16.f32 "
        "{%0,%1,%2,%3},{%4,%5,%6,%7},{%8,%9},{%0,%1,%2,%3};"
        : "+f"(c[0]), "+f"(c[1]), "+f"(c[2]), "+f"(c[3])
        : "r"(a[0]), "r"(a[1]), "r"(a[2]), "r"(a[3]), "r"(b[0]), "r"(b[1]));
}
__device__ __forceinline__ void ldsm4(uint32_t* r, uint32_t addr) {
    asm volatile("ldmatrix.sync.aligned.m8n8.x4.shared.b16 {%0,%1,%2,%3}, [%4];"
        : "=r"(r[0]), "=r"(r[1]), "=r"(r[2]), "=r"(r[3]) : "r"(addr));
}
__device__ __forceinline__ void cpasync16(uint32_t dst, const void* src, uint32_t sz) {
    asm volatile("cp.async.ca.shared.global [%0], [%1], 16, %2;"
                 :: "r"(dst), "l"(src), "r"(sz) : "memory");
}
__device__ __forceinline__ void cp_commit() { asm volatile("cp.async.commit_group;" ::: "memory"); }
__device__ __forceinline__ void cp_wait0()  { asm volatile("cp.async.wait_group 0;" ::: "memory"); }
__device__ __forceinline__ uint32_t pack_bf2(float a, float b) {
    __nv_bfloat162 t = __floats2bfloat162_rn(a, b);
    return *reinterpret_cast<uint32_t*>(&t);
}
__device__ __forceinline__ uint32_t pack_hf2(float a, float b) {
    __half2 t = __floats2half2_rn(a, b);
    return *reinterpret_cast<uint32_t*>(&t);
}
__device__ __forceinline__ float bfr(float x) { return __bfloat162float(__float2bfloat16(x)); }
__device__ __forceinline__ void split_bf(float v, bf16& h, bf16& l) {
    h = __float2bfloat16(v);
    l = __float2bfloat16(v - __bfloat162float(h));
}

// ================= tile 128x128 GEMM (256 thr, warp 64x32) =================
#define R128 80
#define T128_AH 0
#define T128_AL 10240
#define T128_BH 20480
#define T128_BL 30720
#define T128_STG 40960
#define T128_SM (2*T128_STG)

__global__ __launch_bounds__(256, 2)
void tgemm128_kernel(int M, int N, int K,
                  const bf16* __restrict__ Ah, const bf16* __restrict__ Al, int lda, long long sA,
                  const bf16* __restrict__ Bh, const bf16* __restrict__ Bl, int ldb, long long sB,
                  float* __restrict__ Cf, bf16* __restrict__ Ch, bf16* __restrict__ Cl,
                  __half* __restrict__ Cq,
                  int ldc, long long sC,
                  const float* __restrict__ bias,
                  const float* __restrict__ Rp, int ldr, long long sR,
                  float alpha, int relu, int win)
{
    extern __shared__ char smem[];
    uint32_t sbase = smem_u32(smem);
    int tid = threadIdx.x, wid = tid >> 5, lane = tid & 31;
    int grp = lane >> 2, tig = lane & 3;
    int wm = wid & 1, wn = wid >> 1;
    int z = blockIdx.z;
    Ah += (long long)z * sA;  Al += (long long)z * sA;
    Bh += (long long)z * sB;  Bl += (long long)z * sB;
    const float* Rb = Rp ? Rp + (long long)z * sR : nullptr;
    int bm = blockIdx.y * 128;
    int bn = win ? (11 - blockIdx.y + blockIdx.x) * 128 : blockIdx.x * 128;

    const int nch = K >> 5;
    const int sr = tid >> 1, ss = tid & 1;
    const uint32_t sdst = sr * R128 + ss * 32;
    const bf16* gAh = Ah + (size_t)(bm + sr) * lda + ss * 16;
    const bf16* gAl = Al + (size_t)(bm + sr) * lda + ss * 16;
    const bf16* gBh = Bh + (size_t)(bn + sr) * ldb + ss * 16;
    const bf16* gBl = Bl + (size_t)(bn + sr) * ldb + ss * 16;

    const uint32_t lA = (uint32_t)(lane & 15) * R128 + (uint32_t)(lane >> 4) * 16;
    const uint32_t lB = ((uint32_t)((lane >> 4) * 8 + (lane & 7))) * R128 + (uint32_t)((lane >> 3) & 1) * 16;

    float acc[4][4][4];
#pragma unroll
    for (int a = 0; a < 4; a++)
#pragma unroll
        for (int b = 0; b < 4; b++)
#pragma unroll
            for (int r = 0; r < 4; r++) acc[a][b][r] = 0.f;

    {
        uint32_t st = sbase + sdst;
        cpasync16(st + T128_AH,      gAh,     16);
        cpasync16(st + T128_AH + 16, gAh + 8, 16);
        cpasync16(st + T128_AL,      gAl,     16);
        cpasync16(st + T128_AL + 16, gAl + 8, 16);
        cpasync16(st + T128_BH,      gBh,     16);
        cpasync16(st + T128_BH + 16, gBh + 8, 16);
        cpasync16(st + T128_BL,      gBl,     16);
        cpasync16(st + T128_BL + 16, gBl + 8, 16);
        cp_commit();
    }

    for (int c = 0; c < nch; c++) {
        cp_wait0();
        __syncthreads();

        if (c + 1 < nch) {
            uint32_t st = sbase + ((c + 1) & 1) * T128_STG + sdst;
            int k0 = (c + 1) << 5;
            cpasync16(st + T128_AH,      gAh + k0,     16);
            cpasync16(st + T128_AH + 16, gAh + k0 + 8, 16);
            cpasync16(st + T128_AL,      gAl + k0,     16);
            cpasync16(st + T128_AL + 16, gAl + k0 + 8, 16);
            cpasync16(st + T128_BH,      gBh + k0,     16);
            cpasync16(st + T128_BH + 16, gBh + k0 + 8, 16);
            cpasync16(st + T128_BL,      gBl + k0,     16);
            cpasync16(st + T128_BL + 16, gBl + k0 + 8, 16);
        }
        cp_commit();

        uint32_t stg = sbase + (c & 1) * T128_STG;
#pragma unroll
        for (int ks = 0; ks < 2; ks++) {
            uint32_t koff = (uint32_t)ks * 32;
            uint32_t bh[2][4], bl[2][4];
#pragma unroll
            for (int p = 0; p < 2; p++) {
                uint32_t ba = stg + (uint32_t)(wn * 32 + p * 16) * R128 + koff + lB;
                ldsm4(bh[p], ba + T128_BH);
                ldsm4(bl[p], ba + T128_BL);
            }
#pragma unroll
            for (int ms = 0; ms < 4; ms++) {
                uint32_t aa = stg + (uint32_t)(wm * 64 + ms * 16) * R128 + koff + lA;
                uint32_t ah[4], al[4];
                ldsm4(ah, aa + T128_AH);
                ldsm4(al, aa + T128_AL);
#pragma unroll
                for (int ns = 0; ns < 4; ns++) {
                    uint32_t* bhp = &bh[ns >> 1][(ns & 1) * 2];
                    uint32_t* blp = &bl[ns >> 1][(ns & 1) * 2];
                    mma_bf16(acc[ms][ns], ah, bhp);
                    mma_bf16(acc[ms][ns], ah, blp);
                    mma_bf16(acc[ms][ns], al, bhp);
                }
            }
        }
    }

    Cf  = Cf  ? Cf  + (long long)z * sC : nullptr;
    Ch  = Ch  ? Ch  + (long long)z * sC : nullptr;
    Cl  = Cl  ? Cl  + (long long)z * sC : nullptr;
    Cq  = Cq  ? Cq  + (long long)z * sC : nullptr;
    const bool has_bias = (bias != nullptr);
#pragma unroll
    for (int ms = 0; ms < 4; ms++) {
        int row0 = bm + wm * 64 + ms * 16 + grp;
#pragma unroll
        for (int ns = 0; ns < 4; ns++) {
            int col = bn + wn * 32 + ns * 8 + (tig << 1);
#pragma unroll
            for (int h = 0; h < 2; h++) {
                int m = row0 + h * 8;
                float v0 = alpha * acc[ms][ns][h * 2 + 0];
                float v1 = alpha * acc[ms][ns][h * 2 + 1];
                if (has_bias) { v0 += bias[col]; v1 += bias[col + 1]; }
                if (relu) { v0 = fmaxf(v0, 0.f); v1 = fmaxf(v1, 0.f); }
                if (Cq) {
                    *(uint32_t*)(Cq + (size_t)m * ldc + col) = pack_hf2(v0, v1);
                } else if (Cf) {
                    if (Rb) {
                        const float* rp = Rb + (size_t)m * ldr + col;
                        v0 += rp[0]; v1 += rp[1];
                    }
                    *(float2*)(Cf + (size_t)m * ldc + col) = make_float2(v0, v1);
                } else {
                    *(uint32_t*)(Ch + (size_t)m * ldc + col) = pack_bf2(v0, v1);
                    *(uint32_t*)(Cl + (size_t)m * ldc + col) =
                        pack_bf2(v0 - bfr(v0), v1 - bfr(v1));
                }
            }
        }
    }
}

// ================= tile 128x64 GEMM (small-N); alo=0 drops A-lo term =================
#define R64 80
#define T64_AH 0
#define T64_AL 10240
#define T64_BH 20480
#define T64_BL 25600
#define T64_STG 30720
#define T64_SM (2*T64_STG)

__global__ __launch_bounds__(256, 2)
void tgemm64_kernel(int M, int N, int K,
                  const bf16* __restrict__ Ah, const bf16* __restrict__ Al, int lda, long long sA,
                  const bf16* __restrict__ Bh, const bf16* __restrict__ Bl, int ldb, long long sB,
                  float* __restrict__ Cf, bf16* __restrict__ Ch, bf16* __restrict__ Cl,
                  int ldc, long long sC, float alpha, int alo)
{
    extern __shared__ char smem[];
    uint32_t sbase = smem_u32(smem);
    int tid = threadIdx.x, wid = tid >> 5, lane = tid & 31;
    int grp = lane >> 2, tig = lane & 3;
    int wm = wid & 3, wn = wid >> 2;
    int z = blockIdx.z;
    Ah += (long long)z * sA;  Al += (long long)z * sA;
    Bh += (long long)z * sB;  Bl += (long long)z * sB;
    int bm = blockIdx.y * 128;
    int bn = blockIdx.x * 64;

    const int nch = K >> 5;
    const int sra = tid >> 1, ssa = tid & 1;
    const int srb = tid >> 2, ssb = tid & 3;
    const uint32_t dstA = sra * R64 + ssa * 32;
    const uint32_t dstB = srb * R64 + ssb * 16;

    const bf16* gAh = Ah + (size_t)(bm + sra) * lda + ssa * 16;
    const bf16* gAl = Al + (size_t)(bm + sra) * lda + ssa * 16;
    const bf16* gBh = Bh + (size_t)(bn + srb) * ldb + ssb * 8;
    const bf16* gBl = Bl + (size_t)(bn + srb) * ldb + ssb * 8;

    const uint32_t lA = (uint32_t)(lane & 15) * R64 + (uint32_t)(lane >> 4) * 16;
    const uint32_t lB = ((uint32_t)((lane >> 4) * 8 + (lane & 7))) * R64 + (uint32_t)((lane >> 3) & 1) * 16;

    float acc[2][4][4];
#pragma unroll
    for (int a = 0; a < 2; a++)
#pragma unroll
        for (int b = 0; b < 4; b++)
#pragma unroll
            for (int r = 0; r < 4; r++) acc[a][b][r] = 0.f;

    {
        uint32_t st = sbase;
        cpasync16(st + T64_AH + dstA,      gAh,     16);
        cpasync16(st + T64_AH + dstA + 16, gAh + 8, 16);
        if (alo) {
            cpasync16(st + T64_AL + dstA,      gAl,     16);
            cpasync16(st + T64_AL + dstA + 16, gAl + 8, 16);
        }
        cpasync16(st + T64_BH + dstB,      gBh,     16);
        cpasync16(st + T64_BL + dstB,      gBl,     16);
        cp_commit();
    }

    for (int c = 0; c < nch; c++) {
        cp_wait0();
        __syncthreads();

        if (c + 1 < nch) {
            uint32_t st = sbase + ((c + 1) & 1) * T64_STG;
            int k0 = (c + 1) << 5;
            cpasync16(st + T64_AH + dstA,      gAh + k0,     16);
            cpasync16(st + T64_AH + dstA + 16, gAh + k0 + 8, 16);
            if (alo) {
                cpasync16(st + T64_AL + dstA,      gAl + k0,     16);
                cpasync16(st + T64_AL + dstA + 16, gAl + k0 + 8, 16);
            }
            cpasync16(st + T64_BH + dstB,      gBh + k0,     16);
            cpasync16(st + T64_BL + dstB,      gBl + k0,     16);
        }
        cp_commit();

        uint32_t stg = sbase + (c & 1) * T64_STG;
#pragma unroll
        for (int ks = 0; ks < 2; ks++) {
            uint32_t koff = (uint32_t)ks * 32;
            uint32_t bh[2][4], bl[2][4];
#pragma unroll
            for (int p = 0; p < 2; p++) {
                uint32_t ba = stg + (uint32_t)(wn * 32 + p * 16) * R64 + koff + lB;
                ldsm4(bh[p], ba + T64_BH);
                ldsm4(bl[p], ba + T64_BL);
            }
#pragma unroll
            for (int ms = 0; ms < 2; ms++) {
                uint32_t aa = stg + (uint32_t)(wm * 32 + ms * 16) * R64 + koff + lA;
                uint32_t ah[4], al[4];
                ldsm4(ah, aa + T64_AH);
                if (alo) ldsm4(al, aa + T64_AL);
#pragma unroll
                for (int ns = 0; ns < 4; ns++) {
                    uint32_t* bhp = &bh[ns >> 1][(ns & 1) * 2];
                    uint32_t* blp = &bl[ns >> 1][(ns & 1) * 2];
                    mma_bf16(acc[ms][ns], ah, bhp);
                    mma_bf16(acc[ms][ns], ah, blp);
                    if (alo) mma_bf16(acc[ms][ns], al, bhp);
                }
            }
        }
    }

    Cf  = Cf  ? Cf  + (long long)z * sC : nullptr;
    Ch  = Ch  ? Ch  + (long long)z * sC : nullptr;
    Cl  = Cl  ? Cl  + (long long)z * sC : nullptr;
#pragma unroll
    for (int ms = 0; ms < 2; ms++) {
        int row0 = bm + wm * 32 + ms * 16 + grp;
#pragma unroll
        for (int ns = 0; ns < 4; ns++) {
            int col = bn + wn * 32 + ns * 8 + (tig << 1);
#pragma unroll
            for (int h = 0; h < 2; h++) {
                int m = row0 + h * 8;
                float v0 = alpha * acc[ms][ns][h * 2 + 0];
                float v1 = alpha * acc[ms][ns][h * 2 + 1];
                if (Cf) {
                    *(float2*)(Cf + (size_t)m * ldc + col) = make_float2(v0, v1);
                } else {
                    *(uint32_t*)(Ch + (size_t)m * ldc + col) = pack_bf2(v0, v1);
                    *(uint32_t*)(Cl + (size_t)m * ldc + col) =
                        pack_bf2(v0 - bfr(v0), v1 - bfr(v1));
                }
            }
        }
    }
}

// ---------------- split-K combine ----------------
__global__ void combine_kernel(const float* __restrict__ p, int n, int ld,
                               const float* __restrict__ bias, const float* __restrict__ res,
                               float* __restrict__ outf,
                               bf16* __restrict__ oh, bf16* __restrict__ ol,
                               const float* __restrict__ bias2,
                               bf16* __restrict__ oh2, bf16* __restrict__ ol2)
{
    int i4 = blockIdx.x * 256 + threadIdx.x;
    if (i4 * 4 >= n) return;
    int i = i4 * 4;
    float4 a = *(const float4*)(p + i);
    float4 b = *(const float4*)(p + n + i);
    float4 s = make_float4(a.x + b.x, a.y + b.y, a.z + b.z, a.w + b.w);
    int col = i % ld;
    float4 v = s;
    if (bias) {
        float4 bb = *(const float4*)(bias + col);
        v.x += bb.x; v.y += bb.y; v.z += bb.z; v.w += bb.w;
    }
    if (res) {
        float4 r = *(const float4*)(res + i);
        v.x += r.x; v.y += r.y; v.z += r.z; v.w += r.w;
    }
    if (outf) {
        *(float4*)(outf + i) = v;
    } else {
        *(uint32_t*)(oh + i)     = pack_bf2(v.x, v.y);
        *(uint32_t*)(oh + i + 2) = pack_bf2(v.z, v.w);
        *(uint32_t*)(ol + i)     = pack_bf2(v.x - bfr(v.x), v.y - bfr(v.y));
        *(uint32_t*)(ol + i + 2) = pack_bf2(v.z - bfr(v.z), v.w - bfr(v.w));
        if (oh2) {
            float4 b2v = *(const float4*)(bias2 + col);
            float4 u = make_float4(s.x + b2v.x, s.y + b2v.y, s.z + b2v.z, s.w + b2v.w);
            *(uint32_t*)(oh2 + i)     = pack_bf2(u.x, u.y);
            *(uint32_t*)(oh2 + i + 2) = pack_bf2(u.z, u.w);
            *(uint32_t*)(ol2 + i)     = pack_bf2(u.x - bfr(u.x), u.y - bfr(u.y));
            *(uint32_t*)(ol2 + i + 2) = pack_bf2(u.z - bfr(u.z), u.w - bfr(u.w));
        }
    }
}

// ---------------- LayerNorm -> bf16 hi/lo ----------------
__global__ void ln_kernel(const float* __restrict__ x, const float* __restrict__ g,
                          const float* __restrict__ b, bf16* __restrict__ oh, bf16* __restrict__ ol) {
    int row = blockIdx.x;
    const float* xr = x + (size_t)row * CC;
    float s = 0.f, sq = 0.f;
    for (int c = threadIdx.x; c < CC; c += blockDim.x) { float v = xr[c]; s += v; sq += v * v; }
    __shared__ float rs[256], rq[256];
    rs[threadIdx.x] = s; rq[threadIdx.x] = sq; __syncthreads();
    for (int st = 128; st > 0; st >>= 1) {
        if (threadIdx.x < st) { rs[threadIdx.x] += rs[threadIdx.x + st]; rq[threadIdx.x] += rq[threadIdx.x + st]; }
        __syncthreads();
    }
    float mean = rs[0] / CC;
    float var  = rq[0] / CC - mean * mean;
    float rstd = rsqrtf(var + 1e-3f);
    for (int c = threadIdx.x; c < CC; c += blockDim.x) {
        float v = (xr[c] - mean) * rstd * g[c] + b[c];
        bf16 h, l; split_bf(v, h, l);
        oh[(size_t)row * CC + c] = h;
        ol[(size_t)row * CC + c] = l;
    }
}

// ---------------- transpose+convert ----------------
__global__ void cvtT_kernel(const float* __restrict__ in, bf16* __restrict__ oh,
                            bf16* __restrict__ ol, int R, int Cc) {
    __shared__ float t[32][33];
    int bx = blockIdx.x * 32, by = blockIdx.y * 32;
    int x = bx + threadIdx.x;
    for (int i = threadIdx.y; i < 32; i += 8)
        t[i][threadIdx.x] = in[(size_t)(by + i) * Cc + x];
    __syncthreads();
    int xo = by + threadIdx.x;
    for (int i = threadIdx.y; i < 32; i += 8) {
        float v = t[threadIdx.x][i];
        bf16 h, l; split_bf(v, h, l);
        oh[(size_t)(bx + i) * R + xo] = h;
        ol[(size_t)(bx + i) * R + xo] = l;
    }
}

// ---------------- positional features ----------------
__global__ void pos_kernel(bf16* __restrict__ oh, bf16* __restrict__ ol) {
    int row = blockIdx.x;
    int i   = threadIdx.x;
    float p  = (float)(row - (TT - 1));
    float ap = fabsf(p);
    float sg = (p > 0.f) ? 1.f : ((p < 0.f) ? -1.f : 0.f);

    double log2T = log(1536.0) / log(2.0);
    double hl    = exp2(3.0 + (double)i * (log2T - 3.0) / 31.0);
    float coef   = (float)(-0.6931471805599453 / hl);
    float fe     = expf(coef * ap);

    float width = (float)(exp2((double)(i + 1)) - 1.0);
    float fcm   = (width > ap) ? 1.f : 0.f;

    double mean = 48.0 * (double)(i + 1);
    double stdv = 24.0;
    float conc  = (float)((mean / stdv) * (mean / stdv));
    float rate  = (float)(mean / (stdv * stdv));
    double lu   = (double)(conc - 1.f) * log((double)ap) - (double)rate * (double)ap;
    double lnn  = lgamma((double)conc) - (double)conc * log((double)rate);
    float prob  = (float)exp(lu - lnn) + 1e-8f;

    float mx = prob;
#pragma unroll
    for (int o = 16; o > 0; o >>= 1) mx = fmaxf(mx, __shfl_xor_sync(0xffffffffu, mx, o));
    float fg = prob / mx;

    float vals[6] = { fe, fcm, fg, sg * fe, sg * fcm, sg * fg };
    size_t base = (size_t)row * FF;
#pragma unroll
    for (int c = 0; c < 6; c++) {
        bf16 h, l; split_bf(vals[c], h, l);
        oh[base + c * 32 + i] = h;
        ol[base + c * 32 + i] = l;
    }
}

// ---------------- fused shift + softmax (fp16 logits) -> attn bf16 (hi only) ----------------
__global__ void softmax_merge_kernel(const __half* __restrict__ cont, const __half* __restrict__ rel,
                                     bf16* __restrict__ ah) {
    int row = blockIdx.x;
    int q = row % TT;
    const __half* cr = cont + (size_t)row * TT;
    const __half* rr = rel + (size_t)row * LLP + (TT - 1 - q);
    __shared__ float red[512];
    __shared__ float ebuf[TT];
    int t = threadIdx.x;
    float m = -1e30f;
    for (int j2 = t; j2 < TT / 2; j2 += 512) {
        float2 c2 = __half22float2(*(const __half2*)(cr + j2 * 2));
        float s0 = c2.x + __half2float(rr[j2 * 2 + 0]);
        float s1 = c2.y + __half2float(rr[j2 * 2 + 1]);
        ebuf[j2 * 2 + 0] = s0; ebuf[j2 * 2 + 1] = s1;
        m = fmaxf(m, fmaxf(s0, s1));
    }
    red[t] = m; __syncthreads();
    for (int st = 256; st > 0; st >>= 1) {
        if (t < st) red[t] = fmaxf(red[t], red[t + st]);
        __syncthreads();
    }
    m = red[0]; __syncthreads();
    float s = 0.f;
    for (int j = t; j < TT; j += 512) {
        float e = expf(ebuf[j] - m);
        ebuf[j] = e; s += e;
    }
    red[t] = s; __syncthreads();
    for (int st = 256; st > 0; st >>= 1) {
        if (t < st) red[t] += red[t + st];
        __syncthreads();
    }
    float inv = 1.f / red[0];
    for (int j2 = t; j2 < TT / 2; j2 += 512) {
        float v0 = ebuf[j2 * 2] * inv, v1 = ebuf[j2 * 2 + 1] * inv;
        *(uint32_t*)(ah + (size_t)row * TT + j2 * 2) = pack_bf2(v0, v1);
    }
}

// ---------------- host launch ----------------
extern "C" void kernel_launch(void* const* d_in, const int* in_sizes, int n_in,
                              void* d_out, int out_size) {
    const float* x     = (const float*)d_in[0];
    const float* ln1_g = (const float*)d_in[1];
    const float* ln1_b = (const float*)d_in[2];
    const float* ln2_g = (const float*)d_in[3];
    const float* ln2_b = (const float*)d_in[4];
    const float* Wq    = (const float*)d_in[5];
    const float* Wk    = (const float*)d_in[6];
    const float* Wv    = (const float*)d_in[7];
    const float* Wr    = (const float*)d_in[8];
    const float* Wo    = (const float*)d_in[9];
    const float* bo    = (const float*)d_in[10];
    const float* rwb   = (const float*)d_in[11];
    const float* rrb   = (const float*)d_in[12];
    const float* W1    = (const float*)d_in[13];
    const float* b1    = (const float*)d_in[14];
    const float* W2    = (const float*)d_in[15];
    const float* b2    = (const float*)d_in[16];
    float* out = (float*)d_out;

#define GA(sym, ty) ({ void* p_; cudaGetSymbolAddress(&p_, sym); (ty*)p_; })
    bf16 *xnh = GA(g_xn_h, bf16), *xnl = GA(g_xn_l, bf16);
    bf16 *wqh = GA(g_wq_h, bf16), *wql = GA(g_wq_l, bf16);
    bf16 *wkh = GA(g_wk_h, bf16), *wkl = GA(g_wk_l, bf16);
    bf16 *wvh = GA(g_wv_h, bf16), *wvl = GA(g_wv_l, bf16);
    bf16 *wrh = GA(g_wr_h, bf16), *wrl = GA(g_wr_l, bf16);
    bf16 *woh = GA(g_wo_h, bf16), *wol = GA(g_wo_l, bf16);
    bf16 *w1h = GA(g_w1_h, bf16), *w1l = GA(g_w1_l, bf16);
    bf16 *w2h = GA(g_w2_h, bf16), *w2l = GA(g_w2_l, bf16);
    bf16 *qwh = GA(g_qw_h, bf16), *qwl = GA(g_qw_l, bf16);
    bf16 *qrh = GA(g_qr_h, bf16), *qrl = GA(g_qr_l, bf16);
    bf16 *kh  = GA(g_k_h, bf16),  *kl  = GA(g_k_l, bf16);
    bf16 *vTh = GA(g_vT_h, bf16), *vTl = GA(g_vT_l, bf16);
    bf16 *ph  = GA(g_pos_h, bf16),*pl  = GA(g_pos_l, bf16);
    bf16 *rkh = GA(g_rk_h, bf16), *rkl = GA(g_rk_l, bf16);
    __half *cont = GA(g_cont, __half);
    __half *rel  = GA(g_rel, __half);
    bf16 *ath = GA(g_at_h, bf16), *atl = GA(g_at_l, bf16);
    bf16 *oh  = GA(g_o_h, bf16),  *ol  = GA(g_o_l, bf16);
    float *y  = GA(g_y, float);
    bf16 *ynh = GA(g_yn_h, bf16), *ynl = GA(g_yn_l, bf16);
    bf16 *h1h = GA(g_h1_h, bf16), *h1l = GA(g_h1_l, bf16);
    float *pp = GA(g_part, float);
#undef GA

    cudaFuncSetAttribute(tgemm128_kernel, cudaFuncAttributeMaxDynamicSharedMemorySize, T128_SM);
    cudaFuncSetAttribute(tgemm64_kernel,  cudaFuncAttributeMaxDynamicSharedMemorySize, T64_SM);
    dim3 tb(32, 8);
    const int KH = CC / 2;
    const int NB_CC  = (TT*CC/4 + 255)/256;
    const int NB_QK  = (TT*QKC/4 + 255)/256;

    // launch idx 3 = vT-direct split-K tgemm128 (PROFILED)
    ln_kernel<<<TT, 256>>>(x, ln1_g, ln1_b, xnh, xnl);                       // 0
    cvtT_kernel<<<dim3(CC/32, CC/32), tb>>>(Wv, wvh, wvl, CC, CC);           // 1
    pos_kernel<<<LLP, 32>>>(ph, pl);                                         // 2
    // 3: vT = WvT @ xn^T  (A=wvT [CC,CC], B=xn [TT,CC]) split-K x2 -> partials
    tgemm128_kernel<<<dim3(TT/128, CC/128, 2), 256, T128_SM>>>(
        CC, TT, KH, wvh, wvl, CC, KH, xnh, xnl, CC, KH,
        pp, nullptr, nullptr, nullptr, TT, (long long)CC*TT,
        nullptr, nullptr, 0, 0, 1.0f, 0, 0);
    combine_kernel<<<NB_CC, 256>>>(pp, CC*TT, TT, nullptr, nullptr, nullptr,
                                   vTh, vTl, nullptr, nullptr, nullptr);

    cvtT_kernel<<<dim3(QKC/32, CC/32), tb>>>(Wq, wqh, wql, CC, QKC);
    cvtT_kernel<<<dim3(QKC/32, CC/32), tb>>>(Wk, wkh, wkl, CC, QKC);
    cvtT_kernel<<<dim3(QKC/32, FF/32), tb>>>(Wr, wrh, wrl, FF, QKC);
    cvtT_kernel<<<dim3(CC/32, CC/32), tb>>>(Wo, woh, wol, CC, CC);
    cvtT_kernel<<<dim3(2*CC/32, CC/32), tb>>>(W1, w1h, w1l, CC, 2*CC);
    cvtT_kernel<<<dim3(CC/32, 2*CC/32), tb>>>(W2, w2h, w2l, 2*CC, CC);

    // q: split-K x2, combine with dual bias split
    tgemm64_kernel<<<dim3(QKC/64, TT/128, 2), 256, T64_SM>>>(
        TT, QKC, KH, xnh, xnl, CC, KH, wqh, wql, CC, KH,
        pp, nullptr, nullptr, QKC, (long long)TT*QKC, 0.125f, 1);
    combine_kernel<<<NB_QK, 256>>>(pp, TT*QKC, QKC, rwb, nullptr, nullptr,
                                   qwh, qwl, rrb, qrh, qrl);

    // k: split-K x2
    tgemm64_kernel<<<dim3(QKC/64, TT/128, 2), 256, T64_SM>>>(
        TT, QKC, KH, xnh, xnl, CC, KH, wkh, wkl, CC, KH,
        pp, nullptr, nullptr, QKC, (long long)TT*QKC, 1.0f, 1);
    combine_kernel<<<NB_QK, 256>>>(pp, TT*QKC, QKC, nullptr, nullptr, nullptr,
                                   kh, kl, nullptr, nullptr, nullptr);

    // r_k projection
    tgemm64_kernel<<<dim3(QKC/64, LLP/128, 1), 256, T64_SM>>>(
        LLP, QKC, FF, ph, pl, FF, 0, wrh, wrl, FF, 0,
        nullptr, rkh, rkl, QKC, 0, 1.0f, 1);

    // content & rel logits -> fp16
    tgemm128_kernel<<<dim3(TT/128, TT/128, HH), 256, T128_SM>>>(
        TT, TT, HK, qwh, qwl, QKC, HK, kh, kl, QKC, HK,
        nullptr, nullptr, nullptr, cont, TT, (long long)TT*TT,
        nullptr, nullptr, 0, 0, 1.0f, 0, 0);
    tgemm128_kernel<<<dim3(13, TT/128, HH), 256, T128_SM>>>(
        TT, LLP, HK, qrh, qrl, QKC, HK, rkh, rkl, QKC, HK,
        nullptr, nullptr, nullptr, rel, LLP, (long long)TT*LLP,
        nullptr, nullptr, 0, 0, 1.0f, 0, 1);

    // shift + softmax (fp16 in, attn hi only out)
    softmax_merge_kernel<<<HH*TT, 512>>>(cont, rel, ath);

    // attn @ V [tile64, 2-term: attn-lo dropped]
    tgemm64_kernel<<<dim3(3, TT/128, HH), 256, T64_SM>>>(
        TT, HV, TT, ath, atl, TT, (long long)TT*TT, vTh, vTl, TT, (long long)HV*TT,
        nullptr, oh, ol, CC, HV, 1.0f, 0);

    // O projection: split-K x2 + combine (bias bo + residual x)
    tgemm128_kernel<<<dim3(CC/128, TT/128, 2), 256, T128_SM>>>(
        TT, CC, KH, oh, ol, CC, KH, woh, wol, CC, KH,
        pp, nullptr, nullptr, nullptr, CC, (long long)TT*CC,
        nullptr, nullptr, 0, 0, 1.0f, 0, 0);
    combine_kernel<<<NB_CC, 256>>>(pp, TT*CC, CC, bo, x, y,
                                   nullptr, nullptr, nullptr, nullptr, nullptr);

    // LN2 + MLP
    ln_kernel<<<TT, 256>>>(y, ln2_g, ln2_b, ynh, ynl);
    tgemm128_kernel<<<dim3(2*CC/128, TT/128, 1), 256, T128_SM>>>(
        TT, 2*CC, CC, ynh, ynl, CC, 0, w1h, w1l, CC, 0,
        nullptr, h1h, h1l, nullptr, 2*CC, 0, b1, nullptr, 0, 0, 1.0f, 1, 0);
    tgemm128_kernel<<<dim3(CC/128, TT/128, 2), 256, T128_SM>>>(
        TT, CC, CC, h1h, h1l, 2*CC, CC, w2h, w2l, 2*CC, CC,
        pp, nullptr, nullptr, nullptr, CC, (long long)TT*CC,
        nullptr, nullptr, 0, 0, 1.0f, 0, 0);
    combine_kernel<<<NB_CC, 256>>>(pp, TT*CC, CC, b2, y, out,
                                   nullptr, nullptr, nullptr, nullptr, nullptr);
}